// round 7
// baseline (speedup 1.0000x reference)
#include <cuda_runtime.h>
#include <cuda_bf16.h>
#include <cstdint>

// ---------------------------------------------------------------------------
// pointwise (Bahdanau additive) attention, fp32 via split-bf16 mma.sync HMMA
// B=32, T=2048, D=512, U=512
// out layout: [0, B*D) = context ; [B*D, B*D + B*T) = attn
// Round 7: R6 + fixed cross-warp (wn) score combine via smem (was a race).
// ---------------------------------------------------------------------------

#define CB 32
#define CT 2048
#define CD 512
#define CU 512
#define NGROUPS 512              // 32 b x 16 t-tiles
#define GRID_P 148               // persistent CTAs

// scratch (allocation-free rule: __device__ globals)
__device__ float g_scores[CB * CT];
__device__ float g_dec_proj[CB * CU];
__device__ __nv_bfloat16 g_W1hi[CU * CD];             // transposed: [u][k]
__device__ __nv_bfloat16 g_W1lo[CU * CD];
__device__ __nv_bfloat16 g_Ahi[(size_t)CB * CT * CD]; // h_enc hi split
__device__ __nv_bfloat16 g_Alo[(size_t)CB * CT * CD]; // h_enc lo split

// -------------------- PTX helpers --------------------
__device__ __forceinline__ uint32_t smem_u32(const void* p) {
    uint32_t a;
    asm("{ .reg .u64 t; cvta.to.shared.u64 t, %1; cvt.u32.u64 %0, t; }"
        : "=r"(a) : "l"(p));
    return a;
}
__device__ __forceinline__ void cp16(uint32_t dst, const void* src) {
    asm volatile("cp.async.cg.shared.global [%0], [%1], 16;"
                 :: "r"(dst), "l"(src) : "memory");
}
// Dekker split of (a,b) -> packed bf16x2 hi + bf16x2 lo
__device__ __forceinline__ void split2(float a, float b, uint32_t& hi, uint32_t& lo) {
    asm("cvt.rn.bf16x2.f32 %0, %1, %2;" : "=r"(hi) : "f"(b), "f"(a)); // low=a, high=b
    float ha = __uint_as_float(hi << 16);
    float hb = __uint_as_float(hi & 0xffff0000u);
    float la = a - ha, lb = b - hb;
    asm("cvt.rn.bf16x2.f32 %0, %1, %2;" : "=r"(lo) : "f"(lb), "f"(la));
}
__device__ __forceinline__ float fast_tanh(float x) {
    float e;
    asm("ex2.approx.f32 %0, %1;" : "=f"(e) : "f"(x * 2.885390081777927f)); // e^(2x)
    float r;
    asm("rcp.approx.f32 %0, %1;" : "=f"(r) : "f"(e + 1.0f));
    return fmaf(-2.0f, r, 1.0f);
}

#define LDSM4(r, addr)                                                        \
    asm volatile("ldmatrix.sync.aligned.m8n8.x4.shared.b16 {%0,%1,%2,%3}, [%4];" \
                 : "=r"((r)[0]), "=r"((r)[1]), "=r"((r)[2]), "=r"((r)[3])     \
                 : "r"(addr))

#define MMA(d, a, b0, b1)                                                     \
    asm volatile("mma.sync.aligned.m16n8k16.row.col.f32.bf16.bf16.f32 "       \
                 "{%0,%1,%2,%3}, {%4,%5,%6,%7}, {%8,%9}, {%0,%1,%2,%3};"      \
                 : "+f"((d)[0]), "+f"((d)[1]), "+f"((d)[2]), "+f"((d)[3])     \
                 : "r"((a)[0]), "r"((a)[1]), "r"((a)[2]), "r"((a)[3]),        \
                   "r"(b0), "r"(b1))

// -------------------- kernel 0a: split h_enc into bf16 hi/lo --------------------
__global__ void hsplit_kernel(const float* __restrict__ h) {
    size_t i = ((size_t)blockIdx.x * blockDim.x + threadIdx.x) * 2;  // float4 idx
    float4 v0 = ((const float4*)h)[i];
    float4 v1 = ((const float4*)h)[i + 1];
    uint4 hv, lv;
    split2(v0.x, v0.y, hv.x, lv.x);
    split2(v0.z, v0.w, hv.y, lv.y);
    split2(v1.x, v1.y, hv.z, lv.z);
    split2(v1.z, v1.w, hv.w, lv.w);
    ((uint4*)g_Ahi)[i >> 1] = hv;
    ((uint4*)g_Alo)[i >> 1] = lv;
}

// -------------------- kernel 0b: transpose+split W1_enc --------------------
__global__ void w1conv_kernel(const float* __restrict__ W1) {
    __shared__ float t[32][33];
    const int tx = threadIdx.x, ty = threadIdx.y;   // (32, 8)
    const int u0 = blockIdx.x * 32, k0 = blockIdx.y * 32;
#pragma unroll
    for (int i = 0; i < 4; i++)
        t[ty + i * 8][tx] = W1[(size_t)(k0 + ty + i * 8) * CU + u0 + tx];
    __syncthreads();
#pragma unroll
    for (int i = 0; i < 4; i++) {
        int u = u0 + ty + i * 8, k = k0 + tx;
        float v = t[tx][ty + i * 8];
        __nv_bfloat16 h = __float2bfloat16_rn(v);
        g_W1hi[(size_t)u * CD + k] = h;
        g_W1lo[(size_t)u * CD + k] = __float2bfloat16_rn(v - __bfloat162float(h));
    }
}

// -------------------- kernel 1: dec projection --------------------
__global__ __launch_bounds__(512)
void prep_kernel(const float* __restrict__ h_dec,
                 const float* __restrict__ W1,
                 const float* __restrict__ b1) {
    const int b = blockIdx.x;
    const int u = threadIdx.x;              // 512 threads, one u each
    __shared__ float hd[CD];
    hd[u] = h_dec[b * CD + u];
    __syncthreads();

    float acc0 = b1[u], acc1 = 0.f, acc2 = 0.f, acc3 = 0.f;
#pragma unroll 4
    for (int k = 0; k < CD; k += 4) {
        acc0 += hd[k + 0] * W1[(size_t)(CD + k + 0) * CU + u];
        acc1 += hd[k + 1] * W1[(size_t)(CD + k + 1) * CU + u];
        acc2 += hd[k + 2] * W1[(size_t)(CD + k + 2) * CU + u];
        acc3 += hd[k + 3] * W1[(size_t)(CD + k + 3) * CU + u];
    }
    g_dec_proj[b * CU + u] = (acc0 + acc1) + (acc2 + acc3);
}

// -------------------- kernel 2: persistent HMMA split-bf16 score GEMM --------------------
// group = (b, t-tile of 128). Per group: 4 u-tiles x 8 K-chunks = 32 chunks.
// Stage (64KB): Ahi | Alo | Bhi | Blo, each 128x64 bf16, XOR-swizzled. 3 stages.
#define SM_STAGE 65536
#define SM_ALO 16384
#define SM_BHI 32768
#define SM_BLO 49152
#define SM_DP   196608
#define SM_W2   198656
#define SM_COMB 200704           // 128 floats cross-warp score combine
#define SM_TOT  201216

__global__ __launch_bounds__(256, 1)
void score_kernel(const float* __restrict__ W2) {
    extern __shared__ char smem[];
    const uint32_t sbase = smem_u32(smem);
    const int tid = threadIdx.x;
    const int wid = tid >> 5, lid = tid & 31;
    const int wm = wid >> 1, wn = wid & 1;
    const int bid = blockIdx.x;

    // per-lane ldmatrix geometry
    const int rowAf = wm * 32 + (lid & 7) + ((lid >> 3) & 1) * 8;
    const int kselA = lid >> 4;
    const int rowBf = wn * 64 + (lid & 7) + (lid >> 4) * 8;
    const int kselB = (lid >> 3) & 1;
    const int swz = lid & 7;
    const int lid4 = lid & 3, lg = lid >> 2;

    float* sdp = (float*)(smem + SM_DP);
    float* sw2 = (float*)(smem + SM_W2);
    float* comb = (float*)(smem + SM_COMB);
    // W2 is group-invariant: load once
    sw2[tid] = W2[tid];
    sw2[tid + 256] = W2[tid + 256];

    const int ngr = (NGROUPS - bid + GRID_P - 1) / GRID_P;
    const int total = ngr * 32;             // chunks this CTA

    auto load_chunk = [&](int ci, int st) {
        const int g = bid + (ci >> 5) * GRID_P;
        const int b_ = g >> 4, t0_ = (g & 15) * 128;
        const int u0_ = ((ci >> 3) & 3) * 128;
        const int k0 = (ci & 7) * 64;
        const uint32_t sb = sbase + st * SM_STAGE;
        const size_t arow = (size_t)(b_ * CT + t0_);
#pragma unroll
        for (int q = 0; q < 4; q++) {
            int idx = q * 256 + tid;
            int row = idx >> 3, ch = idx & 7;
            uint32_t doff = row * 128 + ((ch ^ (row & 7)) << 4);
            size_t aoff = (arow + row) * CD + k0 + ch * 8;
            size_t boff = (size_t)(u0_ + row) * CD + k0 + ch * 8;
            cp16(sb + doff,          g_Ahi + aoff);
            cp16(sb + SM_ALO + doff, g_Alo + aoff);
            cp16(sb + SM_BHI + doff, g_W1hi + boff);
            cp16(sb + SM_BLO + doff, g_W1lo + boff);
        }
        asm volatile("cp.async.commit_group;" ::: "memory");
    };

    load_chunk(0, 0);
    if (total > 1) load_chunk(1, 1);

    float acc[2][8][4];
    float sAcc[2][2] = {{0.f, 0.f}, {0.f, 0.f}};

#pragma unroll 1
    for (int ci = 0; ci < total; ci++) {
        if (ci < total - 1)
            asm volatile("cp.async.wait_group 1;" ::: "memory");
        else
            asm volatile("cp.async.wait_group 0;" ::: "memory");
        __syncthreads();

        if (ci + 2 < total) load_chunk(ci + 2, (ci + 2) % 3);

        if ((ci & 31) == 0) {               // new group: load dec_proj
            const int g = bid + (ci >> 5) * GRID_P;
            const int b_ = g >> 4;
            sdp[tid] = g_dec_proj[b_ * CU + tid];
            sdp[tid + 256] = g_dec_proj[b_ * CU + tid + 256];
        }
        if ((ci & 7) == 0) {                // new u-tile: reset accumulators
#pragma unroll
            for (int mt = 0; mt < 2; mt++)
#pragma unroll
                for (int nt = 0; nt < 8; nt++)
#pragma unroll
                    for (int j = 0; j < 4; j++) acc[mt][nt][j] = 0.f;
        }

        // ---- compute chunk from stage ci%3 ----
        const uint32_t sb = sbase + (ci % 3) * SM_STAGE;
#pragma unroll
        for (int ks = 0; ks < 4; ks++) {
            uint32_t aH[2][4], aL[2][4];
#pragma unroll
            for (int mt = 0; mt < 2; mt++) {
                uint32_t addr = sb + (rowAf + mt * 16) * 128 +
                                (((ks * 2 + kselA) ^ swz) << 4);
                LDSM4(aH[mt], addr);
                LDSM4(aL[mt], addr + SM_ALO);
            }
#pragma unroll
            for (int ng = 0; ng < 4; ng++) {
                uint32_t baddr = sb + SM_BHI + (rowBf + ng * 16) * 128 +
                                 (((ks * 2 + kselB) ^ swz) << 4);
                uint32_t bH[4], bL[4];
                LDSM4(bH, baddr);
                LDSM4(bL, baddr + 16384);
#pragma unroll
                for (int mt = 0; mt < 2; mt++) {
                    MMA(acc[mt][2 * ng],     aH[mt], bH[0], bH[1]);
                    MMA(acc[mt][2 * ng],     aH[mt], bL[0], bL[1]);
                    MMA(acc[mt][2 * ng],     aL[mt], bH[0], bH[1]);
                    MMA(acc[mt][2 * ng + 1], aH[mt], bH[2], bH[3]);
                    MMA(acc[mt][2 * ng + 1], aH[mt], bL[2], bL[3]);
                    MMA(acc[mt][2 * ng + 1], aL[mt], bH[2], bH[3]);
                }
            }
        }

        // ---- u-tile epilogue: accumulate tanh(acc+dp)*w2 into registers ----
        if ((ci & 7) == 7) {
            const int u0_ = ((ci >> 3) & 3) * 128;
            const int ulb = u0_ + wn * 64 + lid4 * 2;
#pragma unroll
            for (int mt = 0; mt < 2; mt++) {
                float s0 = 0.f, s1 = 0.f;
#pragma unroll
                for (int nt = 0; nt < 8; nt++) {
                    int ul = ulb + nt * 8;
                    float d0 = sdp[ul], d1 = sdp[ul + 1];
                    float w0 = sw2[ul], w1 = sw2[ul + 1];
                    s0 += fast_tanh(acc[mt][nt][0] + d0) * w0 +
                          fast_tanh(acc[mt][nt][1] + d1) * w1;
                    s1 += fast_tanh(acc[mt][nt][2] + d0) * w0 +
                          fast_tanh(acc[mt][nt][3] + d1) * w1;
                }
                sAcc[mt][0] += s0;
                sAcc[mt][1] += s1;
            }
        }

        // ---- group end: reduce in-warp, combine wn halves via smem, store ----
        if ((ci & 31) == 31) {
            const int g = bid + (ci >> 5) * GRID_P;
            const int b_ = g >> 4, t0_ = (g & 15) * 128;
#pragma unroll
            for (int mt = 0; mt < 2; mt++)
#pragma unroll
                for (int j = 0; j < 2; j++) {
                    sAcc[mt][j] += __shfl_xor_sync(0xffffffffu, sAcc[mt][j], 1);
                    sAcc[mt][j] += __shfl_xor_sync(0xffffffffu, sAcc[mt][j], 2);
                }
            if (wn == 1 && lid4 == 0) {
#pragma unroll
                for (int mt = 0; mt < 2; mt++) {
                    int r = wm * 32 + mt * 16 + lg;
                    comb[r] = sAcc[mt][0];
                    comb[r + 8] = sAcc[mt][1];
                }
            }
            __syncthreads();                    // uniform condition: safe
            if (wn == 0 && lid4 == 0) {
#pragma unroll
                for (int mt = 0; mt < 2; mt++) {
                    int r = wm * 32 + mt * 16 + lg;
                    g_scores[b_ * CT + t0_ + r] = sAcc[mt][0] + comb[r];
                    g_scores[b_ * CT + t0_ + r + 8] = sAcc[mt][1] + comb[r + 8];
                }
            }
#pragma unroll
            for (int mt = 0; mt < 2; mt++) {
                sAcc[mt][0] = 0.f;
                sAcc[mt][1] = 0.f;
            }
        }
    }
}

// -------------------- kernel 3: softmax (+ b2, relu) + zero context --------------------
__global__ void softmax_kernel(const float* __restrict__ b2, float* __restrict__ out) {
    const int b = blockIdx.x;
    const int tid = threadIdx.x;
    __shared__ float red[256];
    const float b2v = b2[0];
    float sv[8];

    float mx = 0.f;                        // relu -> scores >= 0
#pragma unroll
    for (int q = 0; q < 8; q++) {
        float s = g_scores[b * CT + q * 256 + tid] + b2v;
        s = s > 0.f ? s : 0.f;
        sv[q] = s;
        mx = fmaxf(mx, s);
    }
    red[tid] = mx; __syncthreads();
    for (int off = 128; off >= 1; off >>= 1) {
        if (tid < off) red[tid] = fmaxf(red[tid], red[tid + off]);
        __syncthreads();
    }
    mx = red[0]; __syncthreads();

    float sum = 0.f;
#pragma unroll
    for (int q = 0; q < 8; q++) {
        float e = expf(sv[q] - mx);
        sv[q] = e;
        sum += e;
    }
    red[tid] = sum; __syncthreads();
    for (int off = 128; off >= 1; off >>= 1) {
        if (tid < off) red[tid] += red[tid + off];
        __syncthreads();
    }
    const float inv = 1.f / red[0];

    float* attn = out + (size_t)CB * CD + (size_t)b * CT;
#pragma unroll
    for (int q = 0; q < 8; q++) attn[q * 256 + tid] = sv[q] * inv;

    for (int i = tid; i < CD; i += 256) out[b * CD + i] = 0.f;
}

// -------------------- kernel 4: context = sum_t attn * h_enc --------------------
__global__ void context_kernel(const float* __restrict__ h_enc, float* __restrict__ out) {
    const int b = blockIdx.y;
    const int t0 = blockIdx.x * 64;
    const int tid = threadIdx.x;           // 128 threads (D/4)
    __shared__ float at[64];
    if (tid < 64) at[tid] = out[(size_t)CB * CD + (size_t)b * CT + t0 + tid];
    __syncthreads();

    const int d = tid * 4;
    float4 acc[4];
#pragma unroll
    for (int j = 0; j < 4; j++) acc[j] = make_float4(0.f, 0.f, 0.f, 0.f);
    const float* hp = h_enc + ((size_t)b * CT + t0) * CD + d;

#pragma unroll 1
    for (int tt = 0; tt < 64; tt += 16) {
        float4 h[16];
#pragma unroll
        for (int j = 0; j < 16; j++)
            h[j] = *(const float4*)(hp + (size_t)(tt + j) * CD);
        float a[16];
#pragma unroll
        for (int j = 0; j < 16; j++) a[j] = at[tt + j];
#pragma unroll
        for (int j = 0; j < 16; j++) {
            acc[j & 3].x += a[j] * h[j].x;
            acc[j & 3].y += a[j] * h[j].y;
            acc[j & 3].z += a[j] * h[j].z;
            acc[j & 3].w += a[j] * h[j].w;
        }
    }
    float4 r;
    r.x = (acc[0].x + acc[1].x) + (acc[2].x + acc[3].x);
    r.y = (acc[0].y + acc[1].y) + (acc[2].y + acc[3].y);
    r.z = (acc[0].z + acc[1].z) + (acc[2].z + acc[3].z);
    r.w = (acc[0].w + acc[1].w) + (acc[2].w + acc[3].w);
    float* cp = out + (size_t)b * CD + d;
    atomicAdd(cp + 0, r.x);
    atomicAdd(cp + 1, r.y);
    atomicAdd(cp + 2, r.z);
    atomicAdd(cp + 3, r.w);
}

// -------------------- host launcher --------------------
extern "C" void kernel_launch(void* const* d_in, const int* in_sizes, int n_in,
                              void* d_out, int out_size) {
    const float* h_enc = (const float*)d_in[0];
    const float* h_dec = (const float*)d_in[1];
    const float* W1    = (const float*)d_in[2];
    const float* b1    = (const float*)d_in[3];
    const float* W2    = (const float*)d_in[4];
    const float* b2    = (const float*)d_in[5];
    float* out = (float*)d_out;

    cudaFuncSetAttribute(score_kernel,
                         cudaFuncAttributeMaxDynamicSharedMemorySize, SM_TOT);

    hsplit_kernel<<<(CB * CT * CD / 8) / 256, 256>>>(h_enc);
    w1conv_kernel<<<dim3(CU / 32, CD / 32), dim3(32, 8)>>>(W1);
    prep_kernel<<<CB, 512>>>(h_dec, W1, b1);
    score_kernel<<<GRID_P, 256, SM_TOT>>>(W2);
    softmax_kernel<<<CB, 256>>>(b2, out);
    context_kernel<<<dim3(CT / 64, CB), 128>>>(h_enc, out);
}

// round 8
// speedup vs baseline: 1.0696x; 1.0696x over previous
#include <cuda_runtime.h>
#include <cuda_bf16.h>
#include <cstdint>

// ---------------------------------------------------------------------------
// pointwise (Bahdanau additive) attention, fp32 via split-bf16 mma.sync HMMA
// B=32, T=2048, D=512, U=512
// out layout: [0, B*D) = context ; [B*D, B*D + B*T) = attn
// Round 8: non-persistent tiles, 3-stage cp.async (1 sync/chunk), fragment
// hoisting + product-major MMA order (no accumulator RAW chains).
// ---------------------------------------------------------------------------

#define CB 32
#define CT 2048
#define CD 512
#define CU 512

// scratch (allocation-free rule: __device__ globals)
__device__ float g_scores[CB * CT];
__device__ float g_dec_proj[CB * CU];
__device__ __nv_bfloat16 g_W1hi[CU * CD];             // transposed: [u][k]
__device__ __nv_bfloat16 g_W1lo[CU * CD];
__device__ __nv_bfloat16 g_Ahi[(size_t)CB * CT * CD]; // h_enc hi split
__device__ __nv_bfloat16 g_Alo[(size_t)CB * CT * CD]; // h_enc lo split

// -------------------- PTX helpers --------------------
__device__ __forceinline__ uint32_t smem_u32(const void* p) {
    uint32_t a;
    asm("{ .reg .u64 t; cvta.to.shared.u64 t, %1; cvt.u32.u64 %0, t; }"
        : "=r"(a) : "l"(p));
    return a;
}
__device__ __forceinline__ void cp16(uint32_t dst, const void* src) {
    asm volatile("cp.async.cg.shared.global [%0], [%1], 16;"
                 :: "r"(dst), "l"(src) : "memory");
}
// Dekker split of (a,b) -> packed bf16x2 hi + bf16x2 lo
__device__ __forceinline__ void split2(float a, float b, uint32_t& hi, uint32_t& lo) {
    asm("cvt.rn.bf16x2.f32 %0, %1, %2;" : "=r"(hi) : "f"(b), "f"(a)); // low=a, high=b
    float ha = __uint_as_float(hi << 16);
    float hb = __uint_as_float(hi & 0xffff0000u);
    float la = a - ha, lb = b - hb;
    asm("cvt.rn.bf16x2.f32 %0, %1, %2;" : "=r"(lo) : "f"(lb), "f"(la));
}
__device__ __forceinline__ float fast_tanh(float x) {
    float e;
    asm("ex2.approx.f32 %0, %1;" : "=f"(e) : "f"(x * 2.885390081777927f)); // e^(2x)
    float r;
    asm("rcp.approx.f32 %0, %1;" : "=f"(r) : "f"(e + 1.0f));
    return fmaf(-2.0f, r, 1.0f);
}

#define LDSM4(r, addr)                                                        \
    asm volatile("ldmatrix.sync.aligned.m8n8.x4.shared.b16 {%0,%1,%2,%3}, [%4];" \
                 : "=r"((r)[0]), "=r"((r)[1]), "=r"((r)[2]), "=r"((r)[3])     \
                 : "r"(addr))

#define MMA(d, a, b0, b1)                                                     \
    asm volatile("mma.sync.aligned.m16n8k16.row.col.f32.bf16.bf16.f32 "       \
                 "{%0,%1,%2,%3}, {%4,%5,%6,%7}, {%8,%9}, {%0,%1,%2,%3};"      \
                 : "+f"((d)[0]), "+f"((d)[1]), "+f"((d)[2]), "+f"((d)[3])     \
                 : "r"((a)[0]), "r"((a)[1]), "r"((a)[2]), "r"((a)[3]),        \
                   "r"(b0), "r"(b1))

// -------------------- kernel 0a: split h_enc into bf16 hi/lo --------------------
__global__ void hsplit_kernel(const float* __restrict__ h) {
    size_t i = ((size_t)blockIdx.x * blockDim.x + threadIdx.x) * 2;  // float4 idx
    float4 v0 = ((const float4*)h)[i];
    float4 v1 = ((const float4*)h)[i + 1];
    uint4 hv, lv;
    split2(v0.x, v0.y, hv.x, lv.x);
    split2(v0.z, v0.w, hv.y, lv.y);
    split2(v1.x, v1.y, hv.z, lv.z);
    split2(v1.z, v1.w, hv.w, lv.w);
    ((uint4*)g_Ahi)[i >> 1] = hv;
    ((uint4*)g_Alo)[i >> 1] = lv;
}

// -------------------- kernel 0b: transpose+split W1_enc --------------------
__global__ void w1conv_kernel(const float* __restrict__ W1) {
    __shared__ float t[32][33];
    const int tx = threadIdx.x, ty = threadIdx.y;   // (32, 8)
    const int u0 = blockIdx.x * 32, k0 = blockIdx.y * 32;
#pragma unroll
    for (int i = 0; i < 4; i++)
        t[ty + i * 8][tx] = W1[(size_t)(k0 + ty + i * 8) * CU + u0 + tx];
    __syncthreads();
#pragma unroll
    for (int i = 0; i < 4; i++) {
        int u = u0 + ty + i * 8, k = k0 + tx;
        float v = t[tx][ty + i * 8];
        __nv_bfloat16 h = __float2bfloat16_rn(v);
        g_W1hi[(size_t)u * CD + k] = h;
        g_W1lo[(size_t)u * CD + k] = __float2bfloat16_rn(v - __bfloat162float(h));
    }
}

// -------------------- kernel 1: dec projection + zero scores --------------------
__global__ __launch_bounds__(512)
void prep_kernel(const float* __restrict__ h_dec,
                 const float* __restrict__ W1,
                 const float* __restrict__ b1) {
    const int b = blockIdx.x;
    const int u = threadIdx.x;              // 512 threads, one u each
    __shared__ float hd[CD];
    hd[u] = h_dec[b * CD + u];
    __syncthreads();

    float acc0 = b1[u], acc1 = 0.f, acc2 = 0.f, acc3 = 0.f;
#pragma unroll 4
    for (int k = 0; k < CD; k += 4) {
        acc0 += hd[k + 0] * W1[(size_t)(CD + k + 0) * CU + u];
        acc1 += hd[k + 1] * W1[(size_t)(CD + k + 1) * CU + u];
        acc2 += hd[k + 2] * W1[(size_t)(CD + k + 2) * CU + u];
        acc3 += hd[k + 3] * W1[(size_t)(CD + k + 3) * CU + u];
    }
    g_dec_proj[b * CU + u] = (acc0 + acc1) + (acc2 + acc3);
#pragma unroll
    for (int t = u; t < CT; t += 512) g_scores[b * CT + t] = 0.f;
}

// -------------------- kernel 2: HMMA split-bf16 score GEMM --------------------
// CTA tile: 128 t x 128 u, K=512 in 8 chunks of 64. Stage (64KB):
// Ahi | Alo | Bhi | Blo, each 128x64 bf16, XOR-swizzled. 3 stages, 1 sync/chunk.
#define SM_STAGE 65536
#define SM_ALO 16384
#define SM_BHI 32768
#define SM_BLO 49152
#define SM_DP  196608
#define SM_W2  197120
#define SM_TOT 197632

__global__ __launch_bounds__(256, 1)
void score_kernel(const float* __restrict__ W2) {
    extern __shared__ char smem[];
    const uint32_t sbase = smem_u32(smem);
    const int tid = threadIdx.x;
    const int wid = tid >> 5, lid = tid & 31;
    const int wm = wid >> 1, wn = wid & 1;
    const int b = blockIdx.y;
    const int ut = blockIdx.x & 3, tt = blockIdx.x >> 2;  // u-fastest: A L2-hot
    const int t0 = tt * 128, u0 = ut * 128;
    const size_t arow = (size_t)(b * CT + t0);

    // per-lane ldmatrix geometry
    const int rowAf = wm * 32 + (lid & 7) + ((lid >> 3) & 1) * 8;
    const int kselA = lid >> 4;
    const int rowBf = wn * 64 + (lid & 7) + (lid >> 4) * 8;
    const int kselB = (lid >> 3) & 1;
    const int swz = lid & 7;

    float* sdp = (float*)(smem + SM_DP);
    float* sw2 = (float*)(smem + SM_W2);
    if (tid < 128) {
        sdp[tid] = g_dec_proj[b * CU + u0 + tid];
        sw2[tid] = W2[u0 + tid];
    }

    auto load_chunk = [&](int c) {
        const int k0 = c * 64;
        const uint32_t sb = sbase + (c % 3) * SM_STAGE;
#pragma unroll
        for (int q = 0; q < 4; q++) {
            int idx = q * 256 + tid;
            int row = idx >> 3, ch = idx & 7;
            uint32_t doff = row * 128 + ((ch ^ (row & 7)) << 4);
            size_t aoff = (arow + row) * CD + k0 + ch * 8;
            size_t boff = (size_t)(u0 + row) * CD + k0 + ch * 8;
            cp16(sb + doff,          g_Ahi + aoff);
            cp16(sb + SM_ALO + doff, g_Alo + aoff);
            cp16(sb + SM_BHI + doff, g_W1hi + boff);
            cp16(sb + SM_BLO + doff, g_W1lo + boff);
        }
        asm volatile("cp.async.commit_group;" ::: "memory");
    };

    load_chunk(0);
    load_chunk(1);

    float acc[2][8][4];
#pragma unroll
    for (int mt = 0; mt < 2; mt++)
#pragma unroll
        for (int nt = 0; nt < 8; nt++)
#pragma unroll
            for (int j = 0; j < 4; j++) acc[mt][nt][j] = 0.f;

#pragma unroll 1
    for (int c = 0; c < 8; c++) {
        if (c < 7)
            asm volatile("cp.async.wait_group 1;" ::: "memory");
        else
            asm volatile("cp.async.wait_group 0;" ::: "memory");
        __syncthreads();
        if (c + 2 < 8) load_chunk(c + 2);

        const uint32_t sb = sbase + (c % 3) * SM_STAGE;
#pragma unroll
        for (int ks = 0; ks < 4; ks++) {
            // ---- hoist all fragments for this k16 step ----
            uint32_t aH[2][4], aL[2][4], bH[4][4], bL[4][4];
#pragma unroll
            for (int mt = 0; mt < 2; mt++) {
                uint32_t addr = sb + (rowAf + mt * 16) * 128 +
                                (((ks * 2 + kselA) ^ swz) << 4);
                LDSM4(aH[mt], addr);
                LDSM4(aL[mt], addr + SM_ALO);
            }
#pragma unroll
            for (int ng = 0; ng < 4; ng++) {
                uint32_t baddr = sb + SM_BHI + (rowBf + ng * 16) * 128 +
                                 (((ks * 2 + kselB) ^ swz) << 4);
                LDSM4(bH[ng], baddr);
                LDSM4(bL[ng], baddr + 16384);
            }
            // ---- product-major MMA order: 16 distinct accumulators per pass ----
#pragma unroll
            for (int ng = 0; ng < 4; ng++)
#pragma unroll
                for (int mt = 0; mt < 2; mt++) {
                    MMA(acc[mt][2 * ng],     aH[mt], bH[ng][0], bH[ng][1]);
                    MMA(acc[mt][2 * ng + 1], aH[mt], bH[ng][2], bH[ng][3]);
                }
#pragma unroll
            for (int ng = 0; ng < 4; ng++)
#pragma unroll
                for (int mt = 0; mt < 2; mt++) {
                    MMA(acc[mt][2 * ng],     aH[mt], bL[ng][0], bL[ng][1]);
                    MMA(acc[mt][2 * ng + 1], aH[mt], bL[ng][2], bL[ng][3]);
                }
#pragma unroll
            for (int ng = 0; ng < 4; ng++)
#pragma unroll
                for (int mt = 0; mt < 2; mt++) {
                    MMA(acc[mt][2 * ng],     aL[mt], bH[ng][0], bH[ng][1]);
                    MMA(acc[mt][2 * ng + 1], aL[mt], bH[ng][2], bH[ng][3]);
                }
        }
    }

    // ---- epilogue: scores[row] += sum_u tanh(acc + dp[u]) * w2[u] ----
    const int lid4 = lid & 3, lg = lid >> 2;
    const int ulb = wn * 64 + lid4 * 2;
#pragma unroll
    for (int mt = 0; mt < 2; mt++) {
        float s0 = 0.f, s1 = 0.f;
#pragma unroll
        for (int nt = 0; nt < 8; nt++) {
            int ul = ulb + nt * 8;
            float d0 = sdp[ul], d1 = sdp[ul + 1];
            float w0 = sw2[ul], w1 = sw2[ul + 1];
            s0 += fast_tanh(acc[mt][nt][0] + d0) * w0 +
                  fast_tanh(acc[mt][nt][1] + d1) * w1;
            s1 += fast_tanh(acc[mt][nt][2] + d0) * w0 +
                  fast_tanh(acc[mt][nt][3] + d1) * w1;
        }
        s0 += __shfl_xor_sync(0xffffffffu, s0, 1);
        s0 += __shfl_xor_sync(0xffffffffu, s0, 2);
        s1 += __shfl_xor_sync(0xffffffffu, s1, 1);
        s1 += __shfl_xor_sync(0xffffffffu, s1, 2);
        if (lid4 == 0) {
            int r = wm * 32 + mt * 16 + lg;
            atomicAdd(&g_scores[b * CT + t0 + r], s0);
            atomicAdd(&g_scores[b * CT + t0 + r + 8], s1);
        }
    }
}

// -------------------- kernel 3: softmax (+ b2, relu) + zero context --------------------
__global__ void softmax_kernel(const float* __restrict__ b2, float* __restrict__ out) {
    const int b = blockIdx.x;
    const int tid = threadIdx.x;
    __shared__ float red[256];
    const float b2v = b2[0];
    float sv[8];

    float mx = 0.f;                        // relu -> scores >= 0
#pragma unroll
    for (int q = 0; q < 8; q++) {
        float s = g_scores[b * CT + q * 256 + tid] + b2v;
        s = s > 0.f ? s : 0.f;
        sv[q] = s;
        mx = fmaxf(mx, s);
    }
    red[tid] = mx; __syncthreads();
    for (int off = 128; off >= 1; off >>= 1) {
        if (tid < off) red[tid] = fmaxf(red[tid], red[tid + off]);
        __syncthreads();
    }
    mx = red[0]; __syncthreads();

    float sum = 0.f;
#pragma unroll
    for (int q = 0; q < 8; q++) {
        float e = expf(sv[q] - mx);
        sv[q] = e;
        sum += e;
    }
    red[tid] = sum; __syncthreads();
    for (int off = 128; off >= 1; off >>= 1) {
        if (tid < off) red[tid] += red[tid + off];
        __syncthreads();
    }
    const float inv = 1.f / red[0];

    float* attn = out + (size_t)CB * CD + (size_t)b * CT;
#pragma unroll
    for (int q = 0; q < 8; q++) attn[q * 256 + tid] = sv[q] * inv;

    for (int i = tid; i < CD; i += 256) out[b * CD + i] = 0.f;
}

// -------------------- kernel 4: context = sum_t attn * h_enc --------------------
__global__ void context_kernel(const float* __restrict__ h_enc, float* __restrict__ out) {
    const int b = blockIdx.y;
    const int t0 = blockIdx.x * 64;
    const int tid = threadIdx.x;           // 128 threads (D/4)
    __shared__ float at[64];
    if (tid < 64) at[tid] = out[(size_t)CB * CD + (size_t)b * CT + t0 + tid];
    __syncthreads();

    const int d = tid * 4;
    float4 acc[4];
#pragma unroll
    for (int j = 0; j < 4; j++) acc[j] = make_float4(0.f, 0.f, 0.f, 0.f);
    const float* hp = h_enc + ((size_t)b * CT + t0) * CD + d;

#pragma unroll 1
    for (int tt = 0; tt < 64; tt += 16) {
        float4 h[16];
#pragma unroll
        for (int j = 0; j < 16; j++)
            h[j] = *(const float4*)(hp + (size_t)(tt + j) * CD);
        float a[16];
#pragma unroll
        for (int j = 0; j < 16; j++) a[j] = at[tt + j];
#pragma unroll
        for (int j = 0; j < 16; j++) {
            acc[j & 3].x += a[j] * h[j].x;
            acc[j & 3].y += a[j] * h[j].y;
            acc[j & 3].z += a[j] * h[j].z;
            acc[j & 3].w += a[j] * h[j].w;
        }
    }
    float4 r;
    r.x = (acc[0].x + acc[1].x) + (acc[2].x + acc[3].x);
    r.y = (acc[0].y + acc[1].y) + (acc[2].y + acc[3].y);
    r.z = (acc[0].z + acc[1].z) + (acc[2].z + acc[3].z);
    r.w = (acc[0].w + acc[1].w) + (acc[2].w + acc[3].w);
    float* cp = out + (size_t)b * CD + d;
    atomicAdd(cp + 0, r.x);
    atomicAdd(cp + 1, r.y);
    atomicAdd(cp + 2, r.z);
    atomicAdd(cp + 3, r.w);
}

// -------------------- host launcher --------------------
extern "C" void kernel_launch(void* const* d_in, const int* in_sizes, int n_in,
                              void* d_out, int out_size) {
    const float* h_enc = (const float*)d_in[0];
    const float* h_dec = (const float*)d_in[1];
    const float* W1    = (const float*)d_in[2];
    const float* b1    = (const float*)d_in[3];
    const float* W2    = (const float*)d_in[4];
    const float* b2    = (const float*)d_in[5];
    float* out = (float*)d_out;

    cudaFuncSetAttribute(score_kernel,
                         cudaFuncAttributeMaxDynamicSharedMemorySize, SM_TOT);

    hsplit_kernel<<<(CB * CT * CD / 8) / 256, 256>>>(h_enc);
    w1conv_kernel<<<dim3(CU / 32, CD / 32), dim3(32, 8)>>>(W1);
    prep_kernel<<<CB, 512>>>(h_dec, W1, b1);
    score_kernel<<<dim3(64, CB), 256, SM_TOT>>>(W2);
    softmax_kernel<<<CB, 256>>>(b2, out);
    context_kernel<<<dim3(CT / 64, CB), 128>>>(h_enc, out);
}

// round 9
// speedup vs baseline: 1.4166x; 1.3245x over previous
#include <cuda_runtime.h>
#include <cuda_fp16.h>
#include <cstdint>

// ---------------------------------------------------------------------------
// pointwise (Bahdanau additive) attention, fp32 via split-fp16 mma.sync HMMA
// B=32, T=2048, D=512, U=512
// out layout: [0, B*D) = context ; [B*D, B*D + B*T) = attn
// Round 9: fp16 2-product split (A single fp16, B split hi/lo), 4-stage
// cp.async pipeline, product-major MMA order.
// ---------------------------------------------------------------------------

#define CB 32
#define CT 2048
#define CD 512
#define CU 512

// scratch (allocation-free rule: __device__ globals)
__device__ float g_scores[CB * CT];
__device__ float g_dec_proj[CB * CU];
__device__ __half g_W1hi[CU * CD];              // transposed: [u][k]
__device__ __half g_W1lo[CU * CD];
__device__ __half g_Ah[(size_t)CB * CT * CD];   // h_enc rounded to fp16

// -------------------- PTX helpers --------------------
__device__ __forceinline__ uint32_t smem_u32(const void* p) {
    uint32_t a;
    asm("{ .reg .u64 t; cvta.to.shared.u64 t, %1; cvt.u32.u64 %0, t; }"
        : "=r"(a) : "l"(p));
    return a;
}
__device__ __forceinline__ void cp16(uint32_t dst, const void* src) {
    asm volatile("cp.async.cg.shared.global [%0], [%1], 16;"
                 :: "r"(dst), "l"(src) : "memory");
}
__device__ __forceinline__ uint32_t packh2(float a, float b) {
    uint32_t r;                                   // low=a, high=b
    asm("cvt.rn.f16x2.f32 %0, %1, %2;" : "=r"(r) : "f"(b), "f"(a));
    return r;
}
__device__ __forceinline__ float fast_tanh(float x) {
    float e;
    asm("ex2.approx.f32 %0, %1;" : "=f"(e) : "f"(x * 2.885390081777927f)); // e^(2x)
    float r;
    asm("rcp.approx.f32 %0, %1;" : "=f"(r) : "f"(e + 1.0f));
    return fmaf(-2.0f, r, 1.0f);
}

#define LDSM4(r, addr)                                                        \
    asm volatile("ldmatrix.sync.aligned.m8n8.x4.shared.b16 {%0,%1,%2,%3}, [%4];" \
                 : "=r"((r)[0]), "=r"((r)[1]), "=r"((r)[2]), "=r"((r)[3])     \
                 : "r"(addr))

#define MMAH(d, a, b0, b1)                                                    \
    asm volatile("mma.sync.aligned.m16n8k16.row.col.f32.f16.f16.f32 "         \
                 "{%0,%1,%2,%3}, {%4,%5,%6,%7}, {%8,%9}, {%0,%1,%2,%3};"      \
                 : "+f"((d)[0]), "+f"((d)[1]), "+f"((d)[2]), "+f"((d)[3])     \
                 : "r"((a)[0]), "r"((a)[1]), "r"((a)[2]), "r"((a)[3]),        \
                   "r"(b0), "r"(b1))

// -------------------- kernel 0a: round h_enc to fp16 --------------------
__global__ void hsplit_kernel(const float* __restrict__ h) {
    size_t i = ((size_t)blockIdx.x * blockDim.x + threadIdx.x) * 2;  // float4 idx
    float4 v0 = ((const float4*)h)[i];
    float4 v1 = ((const float4*)h)[i + 1];
    uint4 o;
    o.x = packh2(v0.x, v0.y);
    o.y = packh2(v0.z, v0.w);
    o.z = packh2(v1.x, v1.y);
    o.w = packh2(v1.z, v1.w);
    ((uint4*)g_Ah)[i >> 1] = o;
}

// -------------------- kernel 0b: transpose + fp16-split W1_enc --------------------
__global__ void w1conv_kernel(const float* __restrict__ W1) {
    __shared__ float t[32][33];
    const int tx = threadIdx.x, ty = threadIdx.y;   // (32, 8)
    const int u0 = blockIdx.x * 32, k0 = blockIdx.y * 32;
#pragma unroll
    for (int i = 0; i < 4; i++)
        t[ty + i * 8][tx] = W1[(size_t)(k0 + ty + i * 8) * CU + u0 + tx];
    __syncthreads();
#pragma unroll
    for (int i = 0; i < 4; i++) {
        int u = u0 + ty + i * 8, k = k0 + tx;
        float v = t[tx][ty + i * 8];
        __half h = __float2half_rn(v);
        g_W1hi[(size_t)u * CD + k] = h;
        g_W1lo[(size_t)u * CD + k] = __float2half_rn(v - __half2float(h));
    }
}

// -------------------- kernel 1: dec projection + zero scores --------------------
__global__ __launch_bounds__(512)
void prep_kernel(const float* __restrict__ h_dec,
                 const float* __restrict__ W1,
                 const float* __restrict__ b1) {
    const int b = blockIdx.x;
    const int u = threadIdx.x;              // 512 threads, one u each
    __shared__ float hd[CD];
    hd[u] = h_dec[b * CD + u];
    __syncthreads();

    float acc0 = b1[u], acc1 = 0.f, acc2 = 0.f, acc3 = 0.f;
#pragma unroll 4
    for (int k = 0; k < CD; k += 4) {
        acc0 += hd[k + 0] * W1[(size_t)(CD + k + 0) * CU + u];
        acc1 += hd[k + 1] * W1[(size_t)(CD + k + 1) * CU + u];
        acc2 += hd[k + 2] * W1[(size_t)(CD + k + 2) * CU + u];
        acc3 += hd[k + 3] * W1[(size_t)(CD + k + 3) * CU + u];
    }
    g_dec_proj[b * CU + u] = (acc0 + acc1) + (acc2 + acc3);
#pragma unroll
    for (int t = u; t < CT; t += 512) g_scores[b * CT + t] = 0.f;
}

// -------------------- kernel 2: HMMA split-fp16 score GEMM --------------------
// CTA tile: 128 t x 128 u, K=512 in 8 chunks of 64. Stage (48KB):
// Ah | Bhi | Blo, each 128x64 fp16 (16KB), XOR-swizzled 128B rows. 4 stages.
#define SM_STAGE 49152
#define SM_BHI 16384
#define SM_BLO 32768
#define SM_DP  196608
#define SM_W2  197120
#define SM_TOT 197632

__global__ __launch_bounds__(256, 1)
void score_kernel(const float* __restrict__ W2) {
    extern __shared__ char smem[];
    const uint32_t sbase = smem_u32(smem);
    const int tid = threadIdx.x;
    const int wid = tid >> 5, lid = tid & 31;
    const int wm = wid >> 1, wn = wid & 1;
    const int b = blockIdx.y;
    const int ut = blockIdx.x & 3, tt = blockIdx.x >> 2;  // u-fastest: A L2-hot
    const int t0 = tt * 128, u0 = ut * 128;
    const size_t arow = (size_t)(b * CT + t0);

    // per-lane ldmatrix geometry
    const int rowAf = wm * 32 + (lid & 7) + ((lid >> 3) & 1) * 8;
    const int kselA = lid >> 4;
    const int rowBf = wn * 64 + (lid & 7) + (lid >> 4) * 8;
    const int kselB = (lid >> 3) & 1;
    const int swz = lid & 7;

    float* sdp = (float*)(smem + SM_DP);
    float* sw2 = (float*)(smem + SM_W2);
    if (tid < 128) {
        sdp[tid] = g_dec_proj[b * CU + u0 + tid];
        sw2[tid] = W2[u0 + tid];
    }

    auto load_chunk = [&](int c) {
        const int k0 = c * 64;
        const uint32_t sb = sbase + (c & 3) * SM_STAGE;
#pragma unroll
        for (int q = 0; q < 4; q++) {
            int idx = q * 256 + tid;
            int row = idx >> 3, ch = idx & 7;
            uint32_t doff = row * 128 + ((ch ^ (row & 7)) << 4);
            size_t aoff = (arow + row) * CD + k0 + ch * 8;
            size_t boff = (size_t)(u0 + row) * CD + k0 + ch * 8;
            cp16(sb + doff,          g_Ah + aoff);
            cp16(sb + SM_BHI + doff, g_W1hi + boff);
            cp16(sb + SM_BLO + doff, g_W1lo + boff);
        }
        asm volatile("cp.async.commit_group;" ::: "memory");
    };

    load_chunk(0);
    load_chunk(1);
    load_chunk(2);

    float acc[2][8][4];
#pragma unroll
    for (int mt = 0; mt < 2; mt++)
#pragma unroll
        for (int nt = 0; nt < 8; nt++)
#pragma unroll
            for (int j = 0; j < 4; j++) acc[mt][nt][j] = 0.f;

#pragma unroll 1
    for (int c = 0; c < 8; c++) {
        if (c <= 5)
            asm volatile("cp.async.wait_group 2;" ::: "memory");
        else if (c == 6)
            asm volatile("cp.async.wait_group 1;" ::: "memory");
        else
            asm volatile("cp.async.wait_group 0;" ::: "memory");
        __syncthreads();
        if (c + 3 < 8) load_chunk(c + 3);

        const uint32_t sb = sbase + (c & 3) * SM_STAGE;
#pragma unroll
        for (int ks = 0; ks < 4; ks++) {
            // ---- hoist all fragments for this k16 step ----
            uint32_t aH[2][4], bH[4][4], bL[4][4];
#pragma unroll
            for (int mt = 0; mt < 2; mt++) {
                uint32_t addr = sb + (rowAf + mt * 16) * 128 +
                                (((ks * 2 + kselA) ^ swz) << 4);
                LDSM4(aH[mt], addr);
            }
#pragma unroll
            for (int ng = 0; ng < 4; ng++) {
                uint32_t baddr = sb + SM_BHI + (rowBf + ng * 16) * 128 +
                                 (((ks * 2 + kselB) ^ swz) << 4);
                LDSM4(bH[ng], baddr);
                LDSM4(bL[ng], baddr + 16384);
            }
            // ---- product-major MMA order: 16 distinct accumulators per pass ----
#pragma unroll
            for (int ng = 0; ng < 4; ng++)
#pragma unroll
                for (int mt = 0; mt < 2; mt++) {
                    MMAH(acc[mt][2 * ng],     aH[mt], bH[ng][0], bH[ng][1]);
                    MMAH(acc[mt][2 * ng + 1], aH[mt], bH[ng][2], bH[ng][3]);
                }
#pragma unroll
            for (int ng = 0; ng < 4; ng++)
#pragma unroll
                for (int mt = 0; mt < 2; mt++) {
                    MMAH(acc[mt][2 * ng],     aH[mt], bL[ng][0], bL[ng][1]);
                    MMAH(acc[mt][2 * ng + 1], aH[mt], bL[ng][2], bL[ng][3]);
                }
        }
    }

    // ---- epilogue: scores[row] += sum_u tanh(acc + dp[u]) * w2[u] ----
    const int lid4 = lid & 3, lg = lid >> 2;
    const int ulb = wn * 64 + lid4 * 2;
#pragma unroll
    for (int mt = 0; mt < 2; mt++) {
        float s0 = 0.f, s1 = 0.f;
#pragma unroll
        for (int nt = 0; nt < 8; nt++) {
            int ul = ulb + nt * 8;
            float d0 = sdp[ul], d1 = sdp[ul + 1];
            float w0 = sw2[ul], w1 = sw2[ul + 1];
            s0 += fast_tanh(acc[mt][nt][0] + d0) * w0 +
                  fast_tanh(acc[mt][nt][1] + d1) * w1;
            s1 += fast_tanh(acc[mt][nt][2] + d0) * w0 +
                  fast_tanh(acc[mt][nt][3] + d1) * w1;
        }
        s0 += __shfl_xor_sync(0xffffffffu, s0, 1);
        s0 += __shfl_xor_sync(0xffffffffu, s0, 2);
        s1 += __shfl_xor_sync(0xffffffffu, s1, 1);
        s1 += __shfl_xor_sync(0xffffffffu, s1, 2);
        if (lid4 == 0) {
            int r = wm * 32 + mt * 16 + lg;
            atomicAdd(&g_scores[b * CT + t0 + r], s0);
            atomicAdd(&g_scores[b * CT + t0 + r + 8], s1);
        }
    }
}

// -------------------- kernel 3: softmax (+ b2, relu) + zero context --------------------
__global__ void softmax_kernel(const float* __restrict__ b2, float* __restrict__ out) {
    const int b = blockIdx.x;
    const int tid = threadIdx.x;
    __shared__ float red[256];
    const float b2v = b2[0];
    float sv[8];

    float mx = 0.f;                        // relu -> scores >= 0
#pragma unroll
    for (int q = 0; q < 8; q++) {
        float s = g_scores[b * CT + q * 256 + tid] + b2v;
        s = s > 0.f ? s : 0.f;
        sv[q] = s;
        mx = fmaxf(mx, s);
    }
    red[tid] = mx; __syncthreads();
    for (int off = 128; off >= 1; off >>= 1) {
        if (tid < off) red[tid] = fmaxf(red[tid], red[tid + off]);
        __syncthreads();
    }
    mx = red[0]; __syncthreads();

    float sum = 0.f;
#pragma unroll
    for (int q = 0; q < 8; q++) {
        float e = expf(sv[q] - mx);
        sv[q] = e;
        sum += e;
    }
    red[tid] = sum; __syncthreads();
    for (int off = 128; off >= 1; off >>= 1) {
        if (tid < off) red[tid] += red[tid + off];
        __syncthreads();
    }
    const float inv = 1.f / red[0];

    float* attn = out + (size_t)CB * CD + (size_t)b * CT;
#pragma unroll
    for (int q = 0; q < 8; q++) attn[q * 256 + tid] = sv[q] * inv;

    for (int i = tid; i < CD; i += 256) out[b * CD + i] = 0.f;
}

// -------------------- kernel 4: context = sum_t attn * h_enc --------------------
__global__ void context_kernel(const float* __restrict__ h_enc, float* __restrict__ out) {
    const int b = blockIdx.y;
    const int t0 = blockIdx.x * 64;
    const int tid = threadIdx.x;           // 128 threads (D/4)
    __shared__ float at[64];
    if (tid < 64) at[tid] = out[(size_t)CB * CD + (size_t)b * CT + t0 + tid];
    __syncthreads();

    const int d = tid * 4;
    float4 acc[4];
#pragma unroll
    for (int j = 0; j < 4; j++) acc[j] = make_float4(0.f, 0.f, 0.f, 0.f);
    const float* hp = h_enc + ((size_t)b * CT + t0) * CD + d;

#pragma unroll 1
    for (int tt = 0; tt < 64; tt += 16) {
        float4 h[16];
#pragma unroll
        for (int j = 0; j < 16; j++)
            h[j] = *(const float4*)(hp + (size_t)(tt + j) * CD);
        float a[16];
#pragma unroll
        for (int j = 0; j < 16; j++) a[j] = at[tt + j];
#pragma unroll
        for (int j = 0; j < 16; j++) {
            acc[j & 3].x += a[j] * h[j].x;
            acc[j & 3].y += a[j] * h[j].y;
            acc[j & 3].z += a[j] * h[j].z;
            acc[j & 3].w += a[j] * h[j].w;
        }
    }
    float4 r;
    r.x = (acc[0].x + acc[1].x) + (acc[2].x + acc[3].x);
    r.y = (acc[0].y + acc[1].y) + (acc[2].y + acc[3].y);
    r.z = (acc[0].z + acc[1].z) + (acc[2].z + acc[3].z);
    r.w = (acc[0].w + acc[1].w) + (acc[2].w + acc[3].w);
    float* cp = out + (size_t)b * CD + d;
    atomicAdd(cp + 0, r.x);
    atomicAdd(cp + 1, r.y);
    atomicAdd(cp + 2, r.z);
    atomicAdd(cp + 3, r.w);
}

// -------------------- host launcher --------------------
extern "C" void kernel_launch(void* const* d_in, const int* in_sizes, int n_in,
                              void* d_out, int out_size) {
    const float* h_enc = (const float*)d_in[0];
    const float* h_dec = (const float*)d_in[1];
    const float* W1    = (const float*)d_in[2];
    const float* b1    = (const float*)d_in[3];
    const float* W2    = (const float*)d_in[4];
    const float* b2    = (const float*)d_in[5];
    float* out = (float*)d_out;

    cudaFuncSetAttribute(score_kernel,
                         cudaFuncAttributeMaxDynamicSharedMemorySize, SM_TOT);

    hsplit_kernel<<<(CB * CT * CD / 8) / 256, 256>>>(h_enc);
    w1conv_kernel<<<dim3(CU / 32, CD / 32), dim3(32, 8)>>>(W1);
    prep_kernel<<<CB, 512>>>(h_dec, W1, b1);
    score_kernel<<<dim3(64, CB), 256, SM_TOT>>>(W2);
    softmax_kernel<<<CB, 256>>>(b2, out);
    context_kernel<<<dim3(CT / 64, CB), 128>>>(h_enc, out);
}

// round 10
// speedup vs baseline: 1.4187x; 1.0015x over previous
#include <cuda_runtime.h>
#include <cuda_fp16.h>
#include <cstdint>

// ---------------------------------------------------------------------------
// pointwise (Bahdanau additive) attention, fp32 via split-fp16 mma.sync HMMA
// B=32, T=2048, D=512, U=512
// out layout: [0, B*D) = context ; [B*D, B*D + B*T) = attn
// Round 9: fp16 2-product split (A single fp16, B split hi/lo), 4-stage
// cp.async pipeline, product-major MMA order.
// ---------------------------------------------------------------------------

#define CB 32
#define CT 2048
#define CD 512
#define CU 512

// scratch (allocation-free rule: __device__ globals)
__device__ float g_scores[CB * CT];
__device__ float g_dec_proj[CB * CU];
__device__ __half g_W1hi[CU * CD];              // transposed: [u][k]
__device__ __half g_W1lo[CU * CD];
__device__ __half g_Ah[(size_t)CB * CT * CD];   // h_enc rounded to fp16

// -------------------- PTX helpers --------------------
__device__ __forceinline__ uint32_t smem_u32(const void* p) {
    uint32_t a;
    asm("{ .reg .u64 t; cvta.to.shared.u64 t, %1; cvt.u32.u64 %0, t; }"
        : "=r"(a) : "l"(p));
    return a;
}
__device__ __forceinline__ void cp16(uint32_t dst, const void* src) {
    asm volatile("cp.async.cg.shared.global [%0], [%1], 16;"
                 :: "r"(dst), "l"(src) : "memory");
}
__device__ __forceinline__ uint32_t packh2(float a, float b) {
    uint32_t r;                                   // low=a, high=b
    asm("cvt.rn.f16x2.f32 %0, %1, %2;" : "=r"(r) : "f"(b), "f"(a));
    return r;
}
__device__ __forceinline__ float fast_tanh(float x) {
    float e;
    asm("ex2.approx.f32 %0, %1;" : "=f"(e) : "f"(x * 2.885390081777927f)); // e^(2x)
    float r;
    asm("rcp.approx.f32 %0, %1;" : "=f"(r) : "f"(e + 1.0f));
    return fmaf(-2.0f, r, 1.0f);
}

#define LDSM4(r, addr)                                                        \
    asm volatile("ldmatrix.sync.aligned.m8n8.x4.shared.b16 {%0,%1,%2,%3}, [%4];" \
                 : "=r"((r)[0]), "=r"((r)[1]), "=r"((r)[2]), "=r"((r)[3])     \
                 : "r"(addr))

#define MMAH(d, a, b0, b1)                                                    \
    asm volatile("mma.sync.aligned.m16n8k16.row.col.f32.f16.f16.f32 "         \
                 "{%0,%1,%2,%3}, {%4,%5,%6,%7}, {%8,%9}, {%0,%1,%2,%3};"      \
                 : "+f"((d)[0]), "+f"((d)[1]), "+f"((d)[2]), "+f"((d)[3])     \
                 : "r"((a)[0]), "r"((a)[1]), "r"((a)[2]), "r"((a)[3]),        \
                   "r"(b0), "r"(b1))

// -------------------- kernel 0a: round h_enc to fp16 --------------------
__global__ void hsplit_kernel(const float* __restrict__ h) {
    size_t i = ((size_t)blockIdx.x * blockDim.x + threadIdx.x) * 2;  // float4 idx
    float4 v0 = ((const float4*)h)[i];
    float4 v1 = ((const float4*)h)[i + 1];
    uint4 o;
    o.x = packh2(v0.x, v0.y);
    o.y = packh2(v0.z, v0.w);
    o.z = packh2(v1.x, v1.y);
    o.w = packh2(v1.z, v1.w);
    ((uint4*)g_Ah)[i >> 1] = o;
}

// -------------------- kernel 0b: transpose + fp16-split W1_enc --------------------
__global__ void w1conv_kernel(const float* __restrict__ W1) {
    __shared__ float t[32][33];
    const int tx = threadIdx.x, ty = threadIdx.y;   // (32, 8)
    const int u0 = blockIdx.x * 32, k0 = blockIdx.y * 32;
#pragma unroll
    for (int i = 0; i < 4; i++)
        t[ty + i * 8][tx] = W1[(size_t)(k0 + ty + i * 8) * CU + u0 + tx];
    __syncthreads();
#pragma unroll
    for (int i = 0; i < 4; i++) {
        int u = u0 + ty + i * 8, k = k0 + tx;
        float v = t[tx][ty + i * 8];
        __half h = __float2half_rn(v);
        g_W1hi[(size_t)u * CD + k] = h;
        g_W1lo[(size_t)u * CD + k] = __float2half_rn(v - __half2float(h));
    }
}

// -------------------- kernel 1: dec projection + zero scores --------------------
__global__ __launch_bounds__(512)
void prep_kernel(const float* __restrict__ h_dec,
                 const float* __restrict__ W1,
                 const float* __restrict__ b1) {
    const int b = blockIdx.x;
    const int u = threadIdx.x;              // 512 threads, one u each
    __shared__ float hd[CD];
    hd[u] = h_dec[b * CD + u];
    __syncthreads();

    float acc0 = b1[u], acc1 = 0.f, acc2 = 0.f, acc3 = 0.f;
#pragma unroll 4
    for (int k = 0; k < CD; k += 4) {
        acc0 += hd[k + 0] * W1[(size_t)(CD + k + 0) * CU + u];
        acc1 += hd[k + 1] * W1[(size_t)(CD + k + 1) * CU + u];
        acc2 += hd[k + 2] * W1[(size_t)(CD + k + 2) * CU + u];
        acc3 += hd[k + 3] * W1[(size_t)(CD + k + 3) * CU + u];
    }
    g_dec_proj[b * CU + u] = (acc0 + acc1) + (acc2 + acc3);
#pragma unroll
    for (int t = u; t < CT; t += 512) g_scores[b * CT + t] = 0.f;
}

// -------------------- kernel 2: HMMA split-fp16 score GEMM --------------------
// CTA tile: 128 t x 128 u, K=512 in 8 chunks of 64. Stage (48KB):
// Ah | Bhi | Blo, each 128x64 fp16 (16KB), XOR-swizzled 128B rows. 4 stages.
#define SM_STAGE 49152
#define SM_BHI 16384
#define SM_BLO 32768
#define SM_DP  196608
#define SM_W2  197120
#define SM_TOT 197632

__global__ __launch_bounds__(256, 1)
void score_kernel(const float* __restrict__ W2) {
    extern __shared__ char smem[];
    const uint32_t sbase = smem_u32(smem);
    const int tid = threadIdx.x;
    const int wid = tid >> 5, lid = tid & 31;
    const int wm = wid >> 1, wn = wid & 1;
    const int b = blockIdx.y;
    const int ut = blockIdx.x & 3, tt = blockIdx.x >> 2;  // u-fastest: A L2-hot
    const int t0 = tt * 128, u0 = ut * 128;
    const size_t arow = (size_t)(b * CT + t0);

    // per-lane ldmatrix geometry
    const int rowAf = wm * 32 + (lid & 7) + ((lid >> 3) & 1) * 8;
    const int kselA = lid >> 4;
    const int rowBf = wn * 64 + (lid & 7) + (lid >> 4) * 8;
    const int kselB = (lid >> 3) & 1;
    const int swz = lid & 7;

    float* sdp = (float*)(smem + SM_DP);
    float* sw2 = (float*)(smem + SM_W2);
    if (tid < 128) {
        sdp[tid] = g_dec_proj[b * CU + u0 + tid];
        sw2[tid] = W2[u0 + tid];
    }

    auto load_chunk = [&](int c) {
        const int k0 = c * 64;
        const uint32_t sb = sbase + (c & 3) * SM_STAGE;
#pragma unroll
        for (int q = 0; q < 4; q++) {
            int idx = q * 256 + tid;
            int row = idx >> 3, ch = idx & 7;
            uint32_t doff = row * 128 + ((ch ^ (row & 7)) << 4);
            size_t aoff = (arow + row) * CD + k0 + ch * 8;
            size_t boff = (size_t)(u0 + row) * CD + k0 + ch * 8;
            cp16(sb + doff,          g_Ah + aoff);
            cp16(sb + SM_BHI + doff, g_W1hi + boff);
            cp16(sb + SM_BLO + doff, g_W1lo + boff);
        }
        asm volatile("cp.async.commit_group;" ::: "memory");
    };

    load_chunk(0);
    load_chunk(1);
    load_chunk(2);

    float acc[2][8][4];
#pragma unroll
    for (int mt = 0; mt < 2; mt++)
#pragma unroll
        for (int nt = 0; nt < 8; nt++)
#pragma unroll
            for (int j = 0; j < 4; j++) acc[mt][nt][j] = 0.f;

#pragma unroll 1
    for (int c = 0; c < 8; c++) {
        if (c <= 5)
            asm volatile("cp.async.wait_group 2;" ::: "memory");
        else if (c == 6)
            asm volatile("cp.async.wait_group 1;" ::: "memory");
        else
            asm volatile("cp.async.wait_group 0;" ::: "memory");
        __syncthreads();
        if (c + 3 < 8) load_chunk(c + 3);

        const uint32_t sb = sbase + (c & 3) * SM_STAGE;
#pragma unroll
        for (int ks = 0; ks < 4; ks++) {
            // ---- hoist all fragments for this k16 step ----
            uint32_t aH[2][4], bH[4][4], bL[4][4];
#pragma unroll
            for (int mt = 0; mt < 2; mt++) {
                uint32_t addr = sb + (rowAf + mt * 16) * 128 +
                                (((ks * 2 + kselA) ^ swz) << 4);
                LDSM4(aH[mt], addr);
            }
#pragma unroll
            for (int ng = 0; ng < 4; ng++) {
                uint32_t baddr = sb + SM_BHI + (rowBf + ng * 16) * 128 +
                                 (((ks * 2 + kselB) ^ swz) << 4);
                LDSM4(bH[ng], baddr);
                LDSM4(bL[ng], baddr + 16384);
            }
            // ---- product-major MMA order: 16 distinct accumulators per pass ----
#pragma unroll
            for (int ng = 0; ng < 4; ng++)
#pragma unroll
                for (int mt = 0; mt < 2; mt++) {
                    MMAH(acc[mt][2 * ng],     aH[mt], bH[ng][0], bH[ng][1]);
                    MMAH(acc[mt][2 * ng + 1], aH[mt], bH[ng][2], bH[ng][3]);
                }
#pragma unroll
            for (int ng = 0; ng < 4; ng++)
#pragma unroll
                for (int mt = 0; mt < 2; mt++) {
                    MMAH(acc[mt][2 * ng],     aH[mt], bL[ng][0], bL[ng][1]);
                    MMAH(acc[mt][2 * ng + 1], aH[mt], bL[ng][2], bL[ng][3]);
                }
        }
    }

    // ---- epilogue: scores[row] += sum_u tanh(acc + dp[u]) * w2[u] ----
    const int lid4 = lid & 3, lg = lid >> 2;
    const int ulb = wn * 64 + lid4 * 2;
#pragma unroll
    for (int mt = 0; mt < 2; mt++) {
        float s0 = 0.f, s1 = 0.f;
#pragma unroll
        for (int nt = 0; nt < 8; nt++) {
            int ul = ulb + nt * 8;
            float d0 = sdp[ul], d1 = sdp[ul + 1];
            float w0 = sw2[ul], w1 = sw2[ul + 1];
            s0 += fast_tanh(acc[mt][nt][0] + d0) * w0 +
                  fast_tanh(acc[mt][nt][1] + d1) * w1;
            s1 += fast_tanh(acc[mt][nt][2] + d0) * w0 +
                  fast_tanh(acc[mt][nt][3] + d1) * w1;
        }
        s0 += __shfl_xor_sync(0xffffffffu, s0, 1);
        s0 += __shfl_xor_sync(0xffffffffu, s0, 2);
        s1 += __shfl_xor_sync(0xffffffffu, s1, 1);
        s1 += __shfl_xor_sync(0xffffffffu, s1, 2);
        if (lid4 == 0) {
            int r = wm * 32 + mt * 16 + lg;
            atomicAdd(&g_scores[b * CT + t0 + r], s0);
            atomicAdd(&g_scores[b * CT + t0 + r + 8], s1);
        }
    }
}

// -------------------- kernel 3: softmax (+ b2, relu) + zero context --------------------
__global__ void softmax_kernel(const float* __restrict__ b2, float* __restrict__ out) {
    const int b = blockIdx.x;
    const int tid = threadIdx.x;
    __shared__ float red[256];
    const float b2v = b2[0];
    float sv[8];

    float mx = 0.f;                        // relu -> scores >= 0
#pragma unroll
    for (int q = 0; q < 8; q++) {
        float s = g_scores[b * CT + q * 256 + tid] + b2v;
        s = s > 0.f ? s : 0.f;
        sv[q] = s;
        mx = fmaxf(mx, s);
    }
    red[tid] = mx; __syncthreads();
    for (int off = 128; off >= 1; off >>= 1) {
        if (tid < off) red[tid] = fmaxf(red[tid], red[tid + off]);
        __syncthreads();
    }
    mx = red[0]; __syncthreads();

    float sum = 0.f;
#pragma unroll
    for (int q = 0; q < 8; q++) {
        float e = expf(sv[q] - mx);
        sv[q] = e;
        sum += e;
    }
    red[tid] = sum; __syncthreads();
    for (int off = 128; off >= 1; off >>= 1) {
        if (tid < off) red[tid] += red[tid + off];
        __syncthreads();
    }
    const float inv = 1.f / red[0];

    float* attn = out + (size_t)CB * CD + (size_t)b * CT;
#pragma unroll
    for (int q = 0; q < 8; q++) attn[q * 256 + tid] = sv[q] * inv;

    for (int i = tid; i < CD; i += 256) out[b * CD + i] = 0.f;
}

// -------------------- kernel 4: context = sum_t attn * h_enc --------------------
__global__ void context_kernel(const float* __restrict__ h_enc, float* __restrict__ out) {
    const int b = blockIdx.y;
    const int t0 = blockIdx.x * 64;
    const int tid = threadIdx.x;           // 128 threads (D/4)
    __shared__ float at[64];
    if (tid < 64) at[tid] = out[(size_t)CB * CD + (size_t)b * CT + t0 + tid];
    __syncthreads();

    const int d = tid * 4;
    float4 acc[4];
#pragma unroll
    for (int j = 0; j < 4; j++) acc[j] = make_float4(0.f, 0.f, 0.f, 0.f);
    const float* hp = h_enc + ((size_t)b * CT + t0) * CD + d;

#pragma unroll 1
    for (int tt = 0; tt < 64; tt += 16) {
        float4 h[16];
#pragma unroll
        for (int j = 0; j < 16; j++)
            h[j] = *(const float4*)(hp + (size_t)(tt + j) * CD);
        float a[16];
#pragma unroll
        for (int j = 0; j < 16; j++) a[j] = at[tt + j];
#pragma unroll
        for (int j = 0; j < 16; j++) {
            acc[j & 3].x += a[j] * h[j].x;
            acc[j & 3].y += a[j] * h[j].y;
            acc[j & 3].z += a[j] * h[j].z;
            acc[j & 3].w += a[j] * h[j].w;
        }
    }
    float4 r;
    r.x = (acc[0].x + acc[1].x) + (acc[2].x + acc[3].x);
    r.y = (acc[0].y + acc[1].y) + (acc[2].y + acc[3].y);
    r.z = (acc[0].z + acc[1].z) + (acc[2].z + acc[3].z);
    r.w = (acc[0].w + acc[1].w) + (acc[2].w + acc[3].w);
    float* cp = out + (size_t)b * CD + d;
    atomicAdd(cp + 0, r.x);
    atomicAdd(cp + 1, r.y);
    atomicAdd(cp + 2, r.z);
    atomicAdd(cp + 3, r.w);
}

// -------------------- host launcher --------------------
extern "C" void kernel_launch(void* const* d_in, const int* in_sizes, int n_in,
                              void* d_out, int out_size) {
    const float* h_enc = (const float*)d_in[0];
    const float* h_dec = (const float*)d_in[1];
    const float* W1    = (const float*)d_in[2];
    const float* b1    = (const float*)d_in[3];
    const float* W2    = (const float*)d_in[4];
    const float* b2    = (const float*)d_in[5];
    float* out = (float*)d_out;

    cudaFuncSetAttribute(score_kernel,
                         cudaFuncAttributeMaxDynamicSharedMemorySize, SM_TOT);

    hsplit_kernel<<<(CB * CT * CD / 8) / 256, 256>>>(h_enc);
    w1conv_kernel<<<dim3(CU / 32, CD / 32), dim3(32, 8)>>>(W1);
    prep_kernel<<<CB, 512>>>(h_dec, W1, b1);
    score_kernel<<<dim3(64, CB), 256, SM_TOT>>>(W2);
    softmax_kernel<<<CB, 256>>>(b2, out);
    context_kernel<<<dim3(CT / 64, CB), 128>>>(h_enc, out);
}

// round 11
// speedup vs baseline: 2.1100x; 1.4873x over previous
#include <cuda_runtime.h>
#include <cuda_fp16.h>
#include <cstdint>

// ---------------------------------------------------------------------------
// pointwise (Bahdanau additive) attention, fp32 via fp16 mma.sync HMMA
// B=32, T=2048, D=512, U=512
// out layout: [0, B*D) = context ; [B*D, B*D + B*T) = attn
// Round 10: single fp16 product (A and W1 both rounded), 3-stage cp.async,
// 32KB stages -> 2 CTAs/SM to cover sync bubbles cross-CTA.
// ---------------------------------------------------------------------------

#define CB 32
#define CT 2048
#define CD 512
#define CU 512

// scratch (allocation-free rule: __device__ globals)
__device__ float g_scores[CB * CT];
__device__ float g_dec_proj[CB * CU];
__device__ __half g_W1h[CU * CD];               // transposed: [u][k], fp16
__device__ __half g_Ah[(size_t)CB * CT * CD];   // h_enc rounded to fp16

// -------------------- PTX helpers --------------------
__device__ __forceinline__ uint32_t smem_u32(const void* p) {
    uint32_t a;
    asm("{ .reg .u64 t; cvta.to.shared.u64 t, %1; cvt.u32.u64 %0, t; }"
        : "=r"(a) : "l"(p));
    return a;
}
__device__ __forceinline__ void cp16(uint32_t dst, const void* src) {
    asm volatile("cp.async.cg.shared.global [%0], [%1], 16;"
                 :: "r"(dst), "l"(src) : "memory");
}
__device__ __forceinline__ uint32_t packh2(float a, float b) {
    uint32_t r;                                   // low=a, high=b
    asm("cvt.rn.f16x2.f32 %0, %1, %2;" : "=r"(r) : "f"(b), "f"(a));
    return r;
}
__device__ __forceinline__ float fast_tanh(float x) {
    float e;
    asm("ex2.approx.f32 %0, %1;" : "=f"(e) : "f"(x * 2.885390081777927f)); // e^(2x)
    float r;
    asm("rcp.approx.f32 %0, %1;" : "=f"(r) : "f"(e + 1.0f));
    return fmaf(-2.0f, r, 1.0f);
}

#define LDSM4(r, addr)                                                        \
    asm volatile("ldmatrix.sync.aligned.m8n8.x4.shared.b16 {%0,%1,%2,%3}, [%4];" \
                 : "=r"((r)[0]), "=r"((r)[1]), "=r"((r)[2]), "=r"((r)[3])     \
                 : "r"(addr))

#define MMAH(d, a, b0, b1)                                                    \
    asm volatile("mma.sync.aligned.m16n8k16.row.col.f32.f16.f16.f32 "         \
                 "{%0,%1,%2,%3}, {%4,%5,%6,%7}, {%8,%9}, {%0,%1,%2,%3};"      \
                 : "+f"((d)[0]), "+f"((d)[1]), "+f"((d)[2]), "+f"((d)[3])     \
                 : "r"((a)[0]), "r"((a)[1]), "r"((a)[2]), "r"((a)[3]),        \
                   "r"(b0), "r"(b1))

// -------------------- kernel 0a: round h_enc to fp16 --------------------
__global__ void hsplit_kernel(const float* __restrict__ h) {
    size_t i = ((size_t)blockIdx.x * blockDim.x + threadIdx.x) * 2;  // float4 idx
    float4 v0 = ((const float4*)h)[i];
    float4 v1 = ((const float4*)h)[i + 1];
    uint4 o;
    o.x = packh2(v0.x, v0.y);
    o.y = packh2(v0.z, v0.w);
    o.z = packh2(v1.x, v1.y);
    o.w = packh2(v1.z, v1.w);
    ((uint4*)g_Ah)[i >> 1] = o;
}

// -------------------- kernel 0b: transpose + round W1_enc --------------------
__global__ void w1conv_kernel(const float* __restrict__ W1) {
    __shared__ float t[32][33];
    const int tx = threadIdx.x, ty = threadIdx.y;   // (32, 8)
    const int u0 = blockIdx.x * 32, k0 = blockIdx.y * 32;
#pragma unroll
    for (int i = 0; i < 4; i++)
        t[ty + i * 8][tx] = W1[(size_t)(k0 + ty + i * 8) * CU + u0 + tx];
    __syncthreads();
#pragma unroll
    for (int i = 0; i < 4; i++) {
        int u = u0 + ty + i * 8, k = k0 + tx;
        g_W1h[(size_t)u * CD + k] = __float2half_rn(t[tx][ty + i * 8]);
    }
}

// -------------------- kernel 1: dec projection + zero scores --------------------
__global__ __launch_bounds__(512)
void prep_kernel(const float* __restrict__ h_dec,
                 const float* __restrict__ W1,
                 const float* __restrict__ b1) {
    const int b = blockIdx.x;
    const int u = threadIdx.x;              // 512 threads, one u each
    __shared__ float hd[CD];
    hd[u] = h_dec[b * CD + u];
    __syncthreads();

    float acc0 = b1[u], acc1 = 0.f, acc2 = 0.f, acc3 = 0.f;
#pragma unroll 4
    for (int k = 0; k < CD; k += 4) {
        acc0 += hd[k + 0] * W1[(size_t)(CD + k + 0) * CU + u];
        acc1 += hd[k + 1] * W1[(size_t)(CD + k + 1) * CU + u];
        acc2 += hd[k + 2] * W1[(size_t)(CD + k + 2) * CU + u];
        acc3 += hd[k + 3] * W1[(size_t)(CD + k + 3) * CU + u];
    }
    g_dec_proj[b * CU + u] = (acc0 + acc1) + (acc2 + acc3);
#pragma unroll
    for (int t = u; t < CT; t += 512) g_scores[b * CT + t] = 0.f;
}

// -------------------- kernel 2: HMMA fp16 score GEMM --------------------
// CTA tile: 128 t x 128 u, K=512 in 8 chunks of 64. Stage (32KB): Ah | Bh,
// each 128x64 fp16 (16KB), XOR-swizzled 128B rows. 3 stages, 2 CTAs/SM.
#define SM_STAGE 32768
#define SM_BH  16384
#define SM_DP  98304
#define SM_W2  98816
#define SM_TOT 99328

__global__ __launch_bounds__(256, 2)
void score_kernel(const float* __restrict__ W2) {
    extern __shared__ char smem[];
    const uint32_t sbase = smem_u32(smem);
    const int tid = threadIdx.x;
    const int wid = tid >> 5, lid = tid & 31;
    const int wm = wid >> 1, wn = wid & 1;
    const int b = blockIdx.y;
    const int ut = blockIdx.x & 3, tt = blockIdx.x >> 2;  // u-fastest: A L2-hot
    const int t0 = tt * 128, u0 = ut * 128;
    const size_t arow = (size_t)(b * CT + t0);

    // per-lane ldmatrix geometry
    const int rowAf = wm * 32 + (lid & 7) + ((lid >> 3) & 1) * 8;
    const int kselA = lid >> 4;
    const int rowBf = wn * 64 + (lid & 7) + (lid >> 4) * 8;
    const int kselB = (lid >> 3) & 1;
    const int swz = lid & 7;

    float* sdp = (float*)(smem + SM_DP);
    float* sw2 = (float*)(smem + SM_W2);
    if (tid < 128) {
        sdp[tid] = g_dec_proj[b * CU + u0 + tid];
        sw2[tid] = W2[u0 + tid];
    }

    auto load_chunk = [&](int c) {
        const int k0 = c * 64;
        const uint32_t sb = sbase + (c % 3) * SM_STAGE;
#pragma unroll
        for (int q = 0; q < 4; q++) {
            int idx = q * 256 + tid;
            int row = idx >> 3, ch = idx & 7;
            uint32_t doff = row * 128 + ((ch ^ (row & 7)) << 4);
            size_t aoff = (arow + row) * CD + k0 + ch * 8;
            size_t boff = (size_t)(u0 + row) * CD + k0 + ch * 8;
            cp16(sb + doff,         g_Ah + aoff);
            cp16(sb + SM_BH + doff, g_W1h + boff);
        }
        asm volatile("cp.async.commit_group;" ::: "memory");
    };

    load_chunk(0);
    load_chunk(1);

    float acc[2][8][4];
#pragma unroll
    for (int mt = 0; mt < 2; mt++)
#pragma unroll
        for (int nt = 0; nt < 8; nt++)
#pragma unroll
            for (int j = 0; j < 4; j++) acc[mt][nt][j] = 0.f;

#pragma unroll 1
    for (int c = 0; c < 8; c++) {
        if (c < 7)
            asm volatile("cp.async.wait_group 1;" ::: "memory");
        else
            asm volatile("cp.async.wait_group 0;" ::: "memory");
        __syncthreads();
        if (c + 2 < 8) load_chunk(c + 2);

        const uint32_t sb = sbase + (c % 3) * SM_STAGE;
#pragma unroll
        for (int ks = 0; ks < 4; ks++) {
            // ---- hoist all fragments for this k16 step ----
            uint32_t aH[2][4], bH[4][4];
#pragma unroll
            for (int mt = 0; mt < 2; mt++) {
                uint32_t addr = sb + (rowAf + mt * 16) * 128 +
                                (((ks * 2 + kselA) ^ swz) << 4);
                LDSM4(aH[mt], addr);
            }
#pragma unroll
            for (int ng = 0; ng < 4; ng++) {
                uint32_t baddr = sb + SM_BH + (rowBf + ng * 16) * 128 +
                                 (((ks * 2 + kselB) ^ swz) << 4);
                LDSM4(bH[ng], baddr);
            }
            // ---- 16 MMAs, all distinct accumulators ----
#pragma unroll
            for (int ng = 0; ng < 4; ng++)
#pragma unroll
                for (int mt = 0; mt < 2; mt++) {
                    MMAH(acc[mt][2 * ng],     aH[mt], bH[ng][0], bH[ng][1]);
                    MMAH(acc[mt][2 * ng + 1], aH[mt], bH[ng][2], bH[ng][3]);
                }
        }
    }

    // ---- epilogue: scores[row] += sum_u tanh(acc + dp[u]) * w2[u] ----
    const int lid4 = lid & 3, lg = lid >> 2;
    const int ulb = wn * 64 + lid4 * 2;
#pragma unroll
    for (int mt = 0; mt < 2; mt++) {
        float s0 = 0.f, s1 = 0.f;
#pragma unroll
        for (int nt = 0; nt < 8; nt++) {
            int ul = ulb + nt * 8;
            float d0 = sdp[ul], d1 = sdp[ul + 1];
            float w0 = sw2[ul], w1 = sw2[ul + 1];
            s0 += fast_tanh(acc[mt][nt][0] + d0) * w0 +
                  fast_tanh(acc[mt][nt][1] + d1) * w1;
            s1 += fast_tanh(acc[mt][nt][2] + d0) * w0 +
                  fast_tanh(acc[mt][nt][3] + d1) * w1;
        }
        s0 += __shfl_xor_sync(0xffffffffu, s0, 1);
        s0 += __shfl_xor_sync(0xffffffffu, s0, 2);
        s1 += __shfl_xor_sync(0xffffffffu, s1, 1);
        s1 += __shfl_xor_sync(0xffffffffu, s1, 2);
        if (lid4 == 0) {
            int r = wm * 32 + mt * 16 + lg;
            atomicAdd(&g_scores[b * CT + t0 + r], s0);
            atomicAdd(&g_scores[b * CT + t0 + r + 8], s1);
        }
    }
}

// -------------------- kernel 3: softmax (+ b2, relu) + zero context --------------------
__global__ void softmax_kernel(const float* __restrict__ b2, float* __restrict__ out) {
    const int b = blockIdx.x;
    const int tid = threadIdx.x;
    __shared__ float red[256];
    const float b2v = b2[0];
    float sv[8];

    float mx = 0.f;                        // relu -> scores >= 0
#pragma unroll
    for (int q = 0; q < 8; q++) {
        float s = g_scores[b * CT + q * 256 + tid] + b2v;
        s = s > 0.f ? s : 0.f;
        sv[q] = s;
        mx = fmaxf(mx, s);
    }
    red[tid] = mx; __syncthreads();
    for (int off = 128; off >= 1; off >>= 1) {
        if (tid < off) red[tid] = fmaxf(red[tid], red[tid + off]);
        __syncthreads();
    }
    mx = red[0]; __syncthreads();

    float sum = 0.f;
#pragma unroll
    for (int q = 0; q < 8; q++) {
        float e = expf(sv[q] - mx);
        sv[q] = e;
        sum += e;
    }
    red[tid] = sum; __syncthreads();
    for (int off = 128; off >= 1; off >>= 1) {
        if (tid < off) red[tid] += red[tid + off];
        __syncthreads();
    }
    const float inv = 1.f / red[0];

    float* attn = out + (size_t)CB * CD + (size_t)b * CT;
#pragma unroll
    for (int q = 0; q < 8; q++) attn[q * 256 + tid] = sv[q] * inv;

    for (int i = tid; i < CD; i += 256) out[b * CD + i] = 0.f;
}

// -------------------- kernel 4: context = sum_t attn * h_enc --------------------
__global__ void context_kernel(const float* __restrict__ h_enc, float* __restrict__ out) {
    const int b = blockIdx.y;
    const int t0 = blockIdx.x * 64;
    const int tid = threadIdx.x;           // 128 threads (D/4)
    __shared__ float at[64];
    if (tid < 64) at[tid] = out[(size_t)CB * CD + (size_t)b * CT + t0 + tid];
    __syncthreads();

    const int d = tid * 4;
    float4 acc[4];
#pragma unroll
    for (int j = 0; j < 4; j++) acc[j] = make_float4(0.f, 0.f, 0.f, 0.f);
    const float* hp = h_enc + ((size_t)b * CT + t0) * CD + d;

#pragma unroll 1
    for (int tt = 0; tt < 64; tt += 16) {
        float4 h[16];
#pragma unroll
        for (int j = 0; j < 16; j++)
            h[j] = *(const float4*)(hp + (size_t)(tt + j) * CD);
        float a[16];
#pragma unroll
        for (int j = 0; j < 16; j++) a[j] = at[tt + j];
#pragma unroll
        for (int j = 0; j < 16; j++) {
            acc[j & 3].x += a[j] * h[j].x;
            acc[j & 3].y += a[j] * h[j].y;
            acc[j & 3].z += a[j] * h[j].z;
            acc[j & 3].w += a[j] * h[j].w;
        }
    }
    float4 r;
    r.x = (acc[0].x + acc[1].x) + (acc[2].x + acc[3].x);
    r.y = (acc[0].y + acc[1].y) + (acc[2].y + acc[3].y);
    r.z = (acc[0].z + acc[1].z) + (acc[2].z + acc[3].z);
    r.w = (acc[0].w + acc[1].w) + (acc[2].w + acc[3].w);
    float* cp = out + (size_t)b * CD + d;
    atomicAdd(cp + 0, r.x);
    atomicAdd(cp + 1, r.y);
    atomicAdd(cp + 2, r.z);
    atomicAdd(cp + 3, r.w);
}

// -------------------- host launcher --------------------
extern "C" void kernel_launch(void* const* d_in, const int* in_sizes, int n_in,
                              void* d_out, int out_size) {
    const float* h_enc = (const float*)d_in[0];
    const float* h_dec = (const float*)d_in[1];
    const float* W1    = (const float*)d_in[2];
    const float* b1    = (const float*)d_in[3];
    const float* W2    = (const float*)d_in[4];
    const float* b2    = (const float*)d_in[5];
    float* out = (float*)d_out;

    cudaFuncSetAttribute(score_kernel,
                         cudaFuncAttributeMaxDynamicSharedMemorySize, SM_TOT);

    hsplit_kernel<<<(CB * CT * CD / 8) / 256, 256>>>(h_enc);
    w1conv_kernel<<<dim3(CU / 32, CD / 32), dim3(32, 8)>>>(W1);
    prep_kernel<<<CB, 512>>>(h_dec, W1, b1);
    score_kernel<<<dim3(64, CB), 256, SM_TOT>>>(W2);
    softmax_kernel<<<CB, 256>>>(b2, out);
    context_kernel<<<dim3(CT / 64, CB), 128>>>(h_enc, out);
}

// round 12
// speedup vs baseline: 2.2589x; 1.0706x over previous
#include <cuda_runtime.h>
#include <cuda_fp16.h>
#include <cstdint>

// ---------------------------------------------------------------------------
// pointwise (Bahdanau additive) attention, fp32 via fp16 mma.sync HMMA
// B=32, T=2048, D=512, U=512
// out layout: [0, B*D) = context ; [B*D, B*D + B*T) = attn
// Round 11: fused prep (hsplit+w1conv+dec_proj in one launch), fp16 context
// read, shfl softmax, loop-invariant addressing in the score GEMM.
// ---------------------------------------------------------------------------

#define CB 32
#define CT 2048
#define CD 512
#define CU 512

// scratch (allocation-free rule: __device__ globals)
__device__ float g_scores[CB * CT];
__device__ float g_dec_proj[CB * CU];
__device__ __half g_W1h[CU * CD];               // transposed: [u][k], fp16
__device__ __half g_Ah[(size_t)CB * CT * CD];   // h_enc rounded to fp16

// -------------------- PTX helpers --------------------
__device__ __forceinline__ uint32_t smem_u32(const void* p) {
    uint32_t a;
    asm("{ .reg .u64 t; cvta.to.shared.u64 t, %1; cvt.u32.u64 %0, t; }"
        : "=r"(a) : "l"(p));
    return a;
}
__device__ __forceinline__ void cp16(uint32_t dst, const void* src) {
    asm volatile("cp.async.cg.shared.global [%0], [%1], 16;"
                 :: "r"(dst), "l"(src) : "memory");
}
__device__ __forceinline__ uint32_t packh2(float a, float b) {
    uint32_t r;                                   // low=a, high=b
    asm("cvt.rn.f16x2.f32 %0, %1, %2;" : "=r"(r) : "f"(b), "f"(a));
    return r;
}
__device__ __forceinline__ float fast_tanh(float x) {
    float e;
    asm("ex2.approx.f32 %0, %1;" : "=f"(e) : "f"(x * 2.885390081777927f)); // e^(2x)
    float r;
    asm("rcp.approx.f32 %0, %1;" : "=f"(r) : "f"(e + 1.0f));
    return fmaf(-2.0f, r, 1.0f);
}

#define LDSM4(r, addr)                                                        \
    asm volatile("ldmatrix.sync.aligned.m8n8.x4.shared.b16 {%0,%1,%2,%3}, [%4];" \
                 : "=r"((r)[0]), "=r"((r)[1]), "=r"((r)[2]), "=r"((r)[3])     \
                 : "r"(addr))

#define MMAH(d, a, b0, b1)                                                    \
    asm volatile("mma.sync.aligned.m16n8k16.row.col.f32.f16.f16.f32 "         \
                 "{%0,%1,%2,%3}, {%4,%5,%6,%7}, {%8,%9}, {%0,%1,%2,%3};"      \
                 : "+f"((d)[0]), "+f"((d)[1]), "+f"((d)[2]), "+f"((d)[3])     \
                 : "r"((a)[0]), "r"((a)[1]), "r"((a)[2]), "r"((a)[3]),        \
                   "r"(b0), "r"(b1))

// -------------------- kernel 0: fused prep --------------------
// blocks [0, 16384): round h_enc to fp16 (8 floats/thread)
// blocks [16384, 16640): transpose + round W1_enc
// blocks [16640, 16704): dec projection + zero scores (2 blocks per b)
#define HS_BLOCKS 16384
#define WC_BLOCKS 256
#define PREP_GRID (HS_BLOCKS + WC_BLOCKS + 64)

__global__ __launch_bounds__(256)
void fused_prep_kernel(const float* __restrict__ h,
                       const float* __restrict__ W1,
                       const float* __restrict__ h_dec,
                       const float* __restrict__ b1) {
    const int blk = blockIdx.x;
    const int tid = threadIdx.x;
    __shared__ float sh[32][33];            // w1conv transpose / prep hd

    if (blk < HS_BLOCKS) {
        size_t i = ((size_t)blk * 256 + tid) * 2;     // float4 index
        float4 v0 = ((const float4*)h)[i];
        float4 v1 = ((const float4*)h)[i + 1];
        uint4 o;
        o.x = packh2(v0.x, v0.y);
        o.y = packh2(v0.z, v0.w);
        o.z = packh2(v1.x, v1.y);
        o.w = packh2(v1.z, v1.w);
        ((uint4*)g_Ah)[i >> 1] = o;
    } else if (blk < HS_BLOCKS + WC_BLOCKS) {
        const int id = blk - HS_BLOCKS;
        const int u0 = (id & 15) * 32, k0 = (id >> 4) * 32;
        const int tx = tid & 31, ty = tid >> 5;
#pragma unroll
        for (int i = 0; i < 4; i++)
            sh[ty + i * 8][tx] = W1[(size_t)(k0 + ty + i * 8) * CU + u0 + tx];
        __syncthreads();
#pragma unroll
        for (int i = 0; i < 4; i++)
            g_W1h[(size_t)(u0 + ty + i * 8) * CD + k0 + tx] =
                __float2half_rn(sh[tx][ty + i * 8]);
    } else {
        const int id = blk - HS_BLOCKS - WC_BLOCKS;
        const int b = id >> 1, uh = id & 1;
        float* hd = &sh[0][0];              // 512 floats
        hd[tid] = h_dec[b * CD + tid];
        hd[tid + 256] = h_dec[b * CD + tid + 256];
        __syncthreads();
        const int u = uh * 256 + tid;
        float a0 = b1[u], a1 = 0.f, a2 = 0.f, a3 = 0.f;
        float a4 = 0.f, a5 = 0.f, a6 = 0.f, a7 = 0.f;
#pragma unroll 4
        for (int k = 0; k < CD; k += 8) {
            a0 += hd[k + 0] * W1[(size_t)(CD + k + 0) * CU + u];
            a1 += hd[k + 1] * W1[(size_t)(CD + k + 1) * CU + u];
            a2 += hd[k + 2] * W1[(size_t)(CD + k + 2) * CU + u];
            a3 += hd[k + 3] * W1[(size_t)(CD + k + 3) * CU + u];
            a4 += hd[k + 4] * W1[(size_t)(CD + k + 4) * CU + u];
            a5 += hd[k + 5] * W1[(size_t)(CD + k + 5) * CU + u];
            a6 += hd[k + 6] * W1[(size_t)(CD + k + 6) * CU + u];
            a7 += hd[k + 7] * W1[(size_t)(CD + k + 7) * CU + u];
        }
        g_dec_proj[b * CU + u] =
            ((a0 + a1) + (a2 + a3)) + ((a4 + a5) + (a6 + a7));
#pragma unroll
        for (int t = uh * 1024 + tid; t < uh * 1024 + 1024; t += 256)
            g_scores[b * CT + t] = 0.f;
    }
}

// -------------------- kernel 1: HMMA fp16 score GEMM --------------------
// CTA tile: 128 t x 128 u, K=512 in 8 chunks of 64. Stage (32KB): Ah | Bh,
// each 128x64 fp16 (16KB), XOR-swizzled 128B rows. 3 stages, 2 CTAs/SM.
#define SM_STAGE 32768
#define SM_BH  16384
#define SM_DP  98304
#define SM_W2  98816
#define SM_TOT 99328

__global__ __launch_bounds__(256, 2)
void score_kernel(const float* __restrict__ W2) {
    extern __shared__ char smem[];
    const uint32_t sbase = smem_u32(smem);
    const int tid = threadIdx.x;
    const int wid = tid >> 5, lid = tid & 31;
    const int wm = wid >> 1, wn = wid & 1;
    const int b = blockIdx.y;
    const int ut = blockIdx.x & 3, tt = blockIdx.x >> 2;  // u-fastest: A L2-hot
    const int t0 = tt * 128, u0 = ut * 128;
    const size_t arow = (size_t)(b * CT + t0);

    // per-lane ldmatrix geometry
    const int rowAf = wm * 32 + (lid & 7) + ((lid >> 3) & 1) * 8;
    const int kselA = lid >> 4;
    const int rowBf = wn * 64 + (lid & 7) + (lid >> 4) * 8;
    const int kselB = (lid >> 3) & 1;
    const int swz = lid & 7;

    // loop-invariant LDSM offsets (relative to stage base)
    uint32_t aoffs[4], boffs[4];
#pragma unroll
    for (int ks = 0; ks < 4; ks++) {
        aoffs[ks] = rowAf * 128 + (((ks * 2 + kselA) ^ swz) << 4);
        boffs[ks] = SM_BH + rowBf * 128 + (((ks * 2 + kselB) ^ swz) << 4);
    }

    // loop-invariant cp.async source pointers + smem dst offsets
    const __half* aptr[4];
    const __half* bptr[4];
    uint32_t doffq[4];
#pragma unroll
    for (int q = 0; q < 4; q++) {
        int idx = q * 256 + tid;
        int row = idx >> 3, ch = idx & 7;
        doffq[q] = row * 128 + ((ch ^ (row & 7)) << 4);
        aptr[q] = g_Ah + (arow + row) * CD + ch * 8;
        bptr[q] = g_W1h + (size_t)(u0 + row) * CD + ch * 8;
    }

    float* sdp = (float*)(smem + SM_DP);
    float* sw2 = (float*)(smem + SM_W2);
    if (tid < 128) {
        sdp[tid] = g_dec_proj[b * CU + u0 + tid];
        sw2[tid] = W2[u0 + tid];
    }

    auto load_chunk = [&](int c) {
        const uint32_t sb = sbase + (c % 3) * SM_STAGE;
        const int kadv = c << 6;            // 64 halves per chunk
#pragma unroll
        for (int q = 0; q < 4; q++) {
            cp16(sb + doffq[q],         aptr[q] + kadv);
            cp16(sb + SM_BH + doffq[q], bptr[q] + kadv);
        }
        asm volatile("cp.async.commit_group;" ::: "memory");
    };

    load_chunk(0);
    load_chunk(1);

    float acc[2][8][4];
#pragma unroll
    for (int mt = 0; mt < 2; mt++)
#pragma unroll
        for (int nt = 0; nt < 8; nt++)
#pragma unroll
            for (int j = 0; j < 4; j++) acc[mt][nt][j] = 0.f;

#pragma unroll 1
    for (int c = 0; c < 8; c++) {
        if (c < 7)
            asm volatile("cp.async.wait_group 1;" ::: "memory");
        else
            asm volatile("cp.async.wait_group 0;" ::: "memory");
        __syncthreads();
        if (c + 2 < 8) load_chunk(c + 2);

        const uint32_t sb = sbase + (c % 3) * SM_STAGE;
#pragma unroll
        for (int ks = 0; ks < 4; ks++) {
            // ---- hoist all fragments for this k16 step ----
            uint32_t aH[2][4], bH[4][4];
#pragma unroll
            for (int mt = 0; mt < 2; mt++)
                LDSM4(aH[mt], sb + aoffs[ks] + mt * 2048);
#pragma unroll
            for (int ng = 0; ng < 4; ng++)
                LDSM4(bH[ng], sb + boffs[ks] + ng * 2048);
            // ---- 16 MMAs, all distinct accumulators ----
#pragma unroll
            for (int ng = 0; ng < 4; ng++)
#pragma unroll
                for (int mt = 0; mt < 2; mt++) {
                    MMAH(acc[mt][2 * ng],     aH[mt], bH[ng][0], bH[ng][1]);
                    MMAH(acc[mt][2 * ng + 1], aH[mt], bH[ng][2], bH[ng][3]);
                }
        }
    }

    // ---- epilogue: scores[row] += sum_u tanh(acc + dp[u]) * w2[u] ----
    const int lid4 = lid & 3, lg = lid >> 2;
    const int ulb = wn * 64 + lid4 * 2;
#pragma unroll
    for (int mt = 0; mt < 2; mt++) {
        float s0 = 0.f, s1 = 0.f;
#pragma unroll
        for (int nt = 0; nt < 8; nt++) {
            int ul = ulb + nt * 8;
            float d0 = sdp[ul], d1 = sdp[ul + 1];
            float w0 = sw2[ul], w1 = sw2[ul + 1];
            s0 += fast_tanh(acc[mt][nt][0] + d0) * w0 +
                  fast_tanh(acc[mt][nt][1] + d1) * w1;
            s1 += fast_tanh(acc[mt][nt][2] + d0) * w0 +
                  fast_tanh(acc[mt][nt][3] + d1) * w1;
        }
        s0 += __shfl_xor_sync(0xffffffffu, s0, 1);
        s0 += __shfl_xor_sync(0xffffffffu, s0, 2);
        s1 += __shfl_xor_sync(0xffffffffu, s1, 1);
        s1 += __shfl_xor_sync(0xffffffffu, s1, 2);
        if (lid4 == 0) {
            int r = wm * 32 + mt * 16 + lg;
            atomicAdd(&g_scores[b * CT + t0 + r], s0);
            atomicAdd(&g_scores[b * CT + t0 + r + 8], s1);
        }
    }
}

// -------------------- kernel 2: softmax (+ b2, relu) + zero context --------------------
__global__ void softmax_kernel(const float* __restrict__ b2, float* __restrict__ out) {
    const int b = blockIdx.x;
    const int tid = threadIdx.x;
    const int wid = tid >> 5, lid = tid & 31;
    __shared__ float wredm[8], wreds[8];
    const float b2v = b2[0];
    float sv[8];

    float mx = 0.f;                        // relu -> scores >= 0
#pragma unroll
    for (int q = 0; q < 8; q++) {
        float s = g_scores[b * CT + q * 256 + tid] + b2v;
        s = s > 0.f ? s : 0.f;
        sv[q] = s;
        mx = fmaxf(mx, s);
    }
#pragma unroll
    for (int off = 16; off >= 1; off >>= 1)
        mx = fmaxf(mx, __shfl_xor_sync(0xffffffffu, mx, off));
    if (lid == 0) wredm[wid] = mx;
    __syncthreads();
    float m = wredm[0];
#pragma unroll
    for (int i = 1; i < 8; i++) m = fmaxf(m, wredm[i]);

    float sum = 0.f;
#pragma unroll
    for (int q = 0; q < 8; q++) {
        float e = expf(sv[q] - m);
        sv[q] = e;
        sum += e;
    }
#pragma unroll
    for (int off = 16; off >= 1; off >>= 1)
        sum += __shfl_xor_sync(0xffffffffu, sum, off);
    if (lid == 0) wreds[wid] = sum;
    __syncthreads();
    float tot = 0.f;
#pragma unroll
    for (int i = 0; i < 8; i++) tot += wreds[i];
    const float inv = 1.f / tot;

    float* attn = out + (size_t)CB * CD + (size_t)b * CT;
#pragma unroll
    for (int q = 0; q < 8; q++) attn[q * 256 + tid] = sv[q] * inv;

    for (int i = tid; i < CD; i += 256) out[b * CD + i] = 0.f;
}

// -------------------- kernel 3: context = sum_t attn * h_enc(fp16) --------------------
__global__ void context_kernel(float* __restrict__ out) {
    const int b = blockIdx.y;
    const int t0 = blockIdx.x * 64;
    const int tid = threadIdx.x;           // 128 threads (D/4)
    __shared__ float at[64];
    if (tid < 64) at[tid] = out[(size_t)CB * CD + (size_t)b * CT + t0 + tid];
    __syncthreads();

    const int d = tid * 4;
    float4 acc[4];
#pragma unroll
    for (int j = 0; j < 4; j++) acc[j] = make_float4(0.f, 0.f, 0.f, 0.f);
    const __half* hp = g_Ah + ((size_t)b * CT + t0) * CD + d;

#pragma unroll 1
    for (int tt = 0; tt < 64; tt += 16) {
        uint2 hv[16];
#pragma unroll
        for (int j = 0; j < 16; j++)
            hv[j] = *(const uint2*)(hp + (size_t)(tt + j) * CD);
        float a[16];
#pragma unroll
        for (int j = 0; j < 16; j++) a[j] = at[tt + j];
#pragma unroll
        for (int j = 0; j < 16; j++) {
            float2 f0 = __half22float2(*(__half2*)&hv[j].x);
            float2 f1 = __half22float2(*(__half2*)&hv[j].y);
            acc[j & 3].x += a[j] * f0.x;
            acc[j & 3].y += a[j] * f0.y;
            acc[j & 3].z += a[j] * f1.x;
            acc[j & 3].w += a[j] * f1.y;
        }
    }
    float4 r;
    r.x = (acc[0].x + acc[1].x) + (acc[2].x + acc[3].x);
    r.y = (acc[0].y + acc[1].y) + (acc[2].y + acc[3].y);
    r.z = (acc[0].z + acc[1].z) + (acc[2].z + acc[3].z);
    r.w = (acc[0].w + acc[1].w) + (acc[2].w + acc[3].w);
    float* cp = out + (size_t)b * CD + d;
    atomicAdd(cp + 0, r.x);
    atomicAdd(cp + 1, r.y);
    atomicAdd(cp + 2, r.z);
    atomicAdd(cp + 3, r.w);
}

// -------------------- host launcher --------------------
extern "C" void kernel_launch(void* const* d_in, const int* in_sizes, int n_in,
                              void* d_out, int out_size) {
    const float* h_enc = (const float*)d_in[0];
    const float* h_dec = (const float*)d_in[1];
    const float* W1    = (const float*)d_in[2];
    const float* b1    = (const float*)d_in[3];
    const float* W2    = (const float*)d_in[4];
    const float* b2    = (const float*)d_in[5];
    float* out = (float*)d_out;

    cudaFuncSetAttribute(score_kernel,
                         cudaFuncAttributeMaxDynamicSharedMemorySize, SM_TOT);

    fused_prep_kernel<<<PREP_GRID, 256>>>(h_enc, W1, h_dec, b1);
    score_kernel<<<dim3(64, CB), 256, SM_TOT>>>(W2);
    softmax_kernel<<<CB, 256>>>(b2, out);
    context_kernel<<<dim3(CT / 64, CB), 128>>>(out);
}

// round 13
// speedup vs baseline: 2.2849x; 1.0115x over previous
#include <cuda_runtime.h>
#include <cuda_fp16.h>
#include <cstdint>

// ---------------------------------------------------------------------------
// pointwise (Bahdanau additive) attention, fp32 via fp16 mma.sync HMMA
// B=32, T=2048, D=512, U=512
// out layout: [0, B*D) = context ; [B*D, B*D + B*T) = attn
// Round 12: high-MLP context kernel (uint4 streams, 4 row-groups), wider
// hsplit loads. Score GEMM unchanged from R11.
// ---------------------------------------------------------------------------

#define CB 32
#define CT 2048
#define CD 512
#define CU 512

// scratch (allocation-free rule: __device__ globals)
__device__ float g_scores[CB * CT];
__device__ float g_dec_proj[CB * CU];
__device__ __half g_W1h[CU * CD];               // transposed: [u][k], fp16
__device__ __half g_Ah[(size_t)CB * CT * CD];   // h_enc rounded to fp16

// -------------------- PTX helpers --------------------
__device__ __forceinline__ uint32_t smem_u32(const void* p) {
    uint32_t a;
    asm("{ .reg .u64 t; cvta.to.shared.u64 t, %1; cvt.u32.u64 %0, t; }"
        : "=r"(a) : "l"(p));
    return a;
}
__device__ __forceinline__ void cp16(uint32_t dst, const void* src) {
    asm volatile("cp.async.cg.shared.global [%0], [%1], 16;"
                 :: "r"(dst), "l"(src) : "memory");
}
__device__ __forceinline__ uint32_t packh2(float a, float b) {
    uint32_t r;                                   // low=a, high=b
    asm("cvt.rn.f16x2.f32 %0, %1, %2;" : "=r"(r) : "f"(b), "f"(a));
    return r;
}
__device__ __forceinline__ float fast_tanh(float x) {
    float e;
    asm("ex2.approx.f32 %0, %1;" : "=f"(e) : "f"(x * 2.885390081777927f)); // e^(2x)
    float r;
    asm("rcp.approx.f32 %0, %1;" : "=f"(r) : "f"(e + 1.0f));
    return fmaf(-2.0f, r, 1.0f);
}

#define LDSM4(r, addr)                                                        \
    asm volatile("ldmatrix.sync.aligned.m8n8.x4.shared.b16 {%0,%1,%2,%3}, [%4];" \
                 : "=r"((r)[0]), "=r"((r)[1]), "=r"((r)[2]), "=r"((r)[3])     \
                 : "r"(addr))

#define MMAH(d, a, b0, b1)                                                    \
    asm volatile("mma.sync.aligned.m16n8k16.row.col.f32.f16.f16.f32 "         \
                 "{%0,%1,%2,%3}, {%4,%5,%6,%7}, {%8,%9}, {%0,%1,%2,%3};"      \
                 : "+f"((d)[0]), "+f"((d)[1]), "+f"((d)[2]), "+f"((d)[3])     \
                 : "r"((a)[0]), "r"((a)[1]), "r"((a)[2]), "r"((a)[3]),        \
                   "r"(b0), "r"(b1))

// -------------------- kernel 0: fused prep --------------------
// blocks [0, 8192): round h_enc to fp16 (16 floats/thread, 4-deep MLP)
// blocks [8192, 8448): transpose + round W1_enc
// blocks [8448, 8512): dec projection + zero scores (2 blocks per b)
#define HS_BLOCKS 8192
#define WC_BLOCKS 256
#define PREP_GRID (HS_BLOCKS + WC_BLOCKS + 64)

__global__ __launch_bounds__(256)
void fused_prep_kernel(const float* __restrict__ h,
                       const float* __restrict__ W1,
                       const float* __restrict__ h_dec,
                       const float* __restrict__ b1) {
    const int blk = blockIdx.x;
    const int tid = threadIdx.x;
    __shared__ float sh[32][33];            // w1conv transpose / prep hd

    if (blk < HS_BLOCKS) {
        size_t i = ((size_t)blk * 256 + tid) * 4;     // float4 index
        float4 v0 = ((const float4*)h)[i];
        float4 v1 = ((const float4*)h)[i + 1];
        float4 v2 = ((const float4*)h)[i + 2];
        float4 v3 = ((const float4*)h)[i + 3];
        uint4 o0, o1;
        o0.x = packh2(v0.x, v0.y);
        o0.y = packh2(v0.z, v0.w);
        o0.z = packh2(v1.x, v1.y);
        o0.w = packh2(v1.z, v1.w);
        o1.x = packh2(v2.x, v2.y);
        o1.y = packh2(v2.z, v2.w);
        o1.z = packh2(v3.x, v3.y);
        o1.w = packh2(v3.z, v3.w);
        ((uint4*)g_Ah)[(i >> 1)]     = o0;
        ((uint4*)g_Ah)[(i >> 1) + 1] = o1;
    } else if (blk < HS_BLOCKS + WC_BLOCKS) {
        const int id = blk - HS_BLOCKS;
        const int u0 = (id & 15) * 32, k0 = (id >> 4) * 32;
        const int tx = tid & 31, ty = tid >> 5;
#pragma unroll
        for (int i = 0; i < 4; i++)
            sh[ty + i * 8][tx] = W1[(size_t)(k0 + ty + i * 8) * CU + u0 + tx];
        __syncthreads();
#pragma unroll
        for (int i = 0; i < 4; i++)
            g_W1h[(size_t)(u0 + ty + i * 8) * CD + k0 + tx] =
                __float2half_rn(sh[tx][ty + i * 8]);
    } else {
        const int id = blk - HS_BLOCKS - WC_BLOCKS;
        const int b = id >> 1, uh = id & 1;
        float* hd = &sh[0][0];              // 512 floats
        hd[tid] = h_dec[b * CD + tid];
        hd[tid + 256] = h_dec[b * CD + tid + 256];
        __syncthreads();
        const int u = uh * 256 + tid;
        float a0 = b1[u], a1 = 0.f, a2 = 0.f, a3 = 0.f;
        float a4 = 0.f, a5 = 0.f, a6 = 0.f, a7 = 0.f;
#pragma unroll 4
        for (int k = 0; k < CD; k += 8) {
            a0 += hd[k + 0] * W1[(size_t)(CD + k + 0) * CU + u];
            a1 += hd[k + 1] * W1[(size_t)(CD + k + 1) * CU + u];
            a2 += hd[k + 2] * W1[(size_t)(CD + k + 2) * CU + u];
            a3 += hd[k + 3] * W1[(size_t)(CD + k + 3) * CU + u];
            a4 += hd[k + 4] * W1[(size_t)(CD + k + 4) * CU + u];
            a5 += hd[k + 5] * W1[(size_t)(CD + k + 5) * CU + u];
            a6 += hd[k + 6] * W1[(size_t)(CD + k + 6) * CU + u];
            a7 += hd[k + 7] * W1[(size_t)(CD + k + 7) * CU + u];
        }
        g_dec_proj[b * CU + u] =
            ((a0 + a1) + (a2 + a3)) + ((a4 + a5) + (a6 + a7));
#pragma unroll
        for (int t = uh * 1024 + tid; t < uh * 1024 + 1024; t += 256)
            g_scores[b * CT + t] = 0.f;
    }
}

// -------------------- kernel 1: HMMA fp16 score GEMM --------------------
// CTA tile: 128 t x 128 u, K=512 in 8 chunks of 64. Stage (32KB): Ah | Bh,
// each 128x64 fp16 (16KB), XOR-swizzled 128B rows. 3 stages, 2 CTAs/SM.
#define SM_STAGE 32768
#define SM_BH  16384
#define SM_DP  98304
#define SM_W2  98816
#define SM_TOT 99328

__global__ __launch_bounds__(256, 2)
void score_kernel(const float* __restrict__ W2) {
    extern __shared__ char smem[];
    const uint32_t sbase = smem_u32(smem);
    const int tid = threadIdx.x;
    const int wid = tid >> 5, lid = tid & 31;
    const int wm = wid >> 1, wn = wid & 1;
    const int b = blockIdx.y;
    const int ut = blockIdx.x & 3, tt = blockIdx.x >> 2;  // u-fastest: A L2-hot
    const int t0 = tt * 128, u0 = ut * 128;
    const size_t arow = (size_t)(b * CT + t0);

    // per-lane ldmatrix geometry
    const int rowAf = wm * 32 + (lid & 7) + ((lid >> 3) & 1) * 8;
    const int kselA = lid >> 4;
    const int rowBf = wn * 64 + (lid & 7) + (lid >> 4) * 8;
    const int kselB = (lid >> 3) & 1;
    const int swz = lid & 7;

    // loop-invariant LDSM offsets (relative to stage base)
    uint32_t aoffs[4], boffs[4];
#pragma unroll
    for (int ks = 0; ks < 4; ks++) {
        aoffs[ks] = rowAf * 128 + (((ks * 2 + kselA) ^ swz) << 4);
        boffs[ks] = SM_BH + rowBf * 128 + (((ks * 2 + kselB) ^ swz) << 4);
    }

    // loop-invariant cp.async source pointers + smem dst offsets
    const __half* aptr[4];
    const __half* bptr[4];
    uint32_t doffq[4];
#pragma unroll
    for (int q = 0; q < 4; q++) {
        int idx = q * 256 + tid;
        int row = idx >> 3, ch = idx & 7;
        doffq[q] = row * 128 + ((ch ^ (row & 7)) << 4);
        aptr[q] = g_Ah + (arow + row) * CD + ch * 8;
        bptr[q] = g_W1h + (size_t)(u0 + row) * CD + ch * 8;
    }

    float* sdp = (float*)(smem + SM_DP);
    float* sw2 = (float*)(smem + SM_W2);
    if (tid < 128) {
        sdp[tid] = g_dec_proj[b * CU + u0 + tid];
        sw2[tid] = W2[u0 + tid];
    }

    auto load_chunk = [&](int c) {
        const uint32_t sb = sbase + (c % 3) * SM_STAGE;
        const int kadv = c << 6;            // 64 halves per chunk
#pragma unroll
        for (int q = 0; q < 4; q++) {
            cp16(sb + doffq[q],         aptr[q] + kadv);
            cp16(sb + SM_BH + doffq[q], bptr[q] + kadv);
        }
        asm volatile("cp.async.commit_group;" ::: "memory");
    };

    load_chunk(0);
    load_chunk(1);

    float acc[2][8][4];
#pragma unroll
    for (int mt = 0; mt < 2; mt++)
#pragma unroll
        for (int nt = 0; nt < 8; nt++)
#pragma unroll
            for (int j = 0; j < 4; j++) acc[mt][nt][j] = 0.f;

#pragma unroll 1
    for (int c = 0; c < 8; c++) {
        if (c < 7)
            asm volatile("cp.async.wait_group 1;" ::: "memory");
        else
            asm volatile("cp.async.wait_group 0;" ::: "memory");
        __syncthreads();
        if (c + 2 < 8) load_chunk(c + 2);

        const uint32_t sb = sbase + (c % 3) * SM_STAGE;
#pragma unroll
        for (int ks = 0; ks < 4; ks++) {
            // ---- hoist all fragments for this k16 step ----
            uint32_t aH[2][4], bH[4][4];
#pragma unroll
            for (int mt = 0; mt < 2; mt++)
                LDSM4(aH[mt], sb + aoffs[ks] + mt * 2048);
#pragma unroll
            for (int ng = 0; ng < 4; ng++)
                LDSM4(bH[ng], sb + boffs[ks] + ng * 2048);
            // ---- 16 MMAs, all distinct accumulators ----
#pragma unroll
            for (int ng = 0; ng < 4; ng++)
#pragma unroll
                for (int mt = 0; mt < 2; mt++) {
                    MMAH(acc[mt][2 * ng],     aH[mt], bH[ng][0], bH[ng][1]);
                    MMAH(acc[mt][2 * ng + 1], aH[mt], bH[ng][2], bH[ng][3]);
                }
        }
    }

    // ---- epilogue: scores[row] += sum_u tanh(acc + dp[u]) * w2[u] ----
    const int lid4 = lid & 3, lg = lid >> 2;
    const int ulb = wn * 64 + lid4 * 2;
#pragma unroll
    for (int mt = 0; mt < 2; mt++) {
        float s0 = 0.f, s1 = 0.f;
#pragma unroll
        for (int nt = 0; nt < 8; nt++) {
            int ul = ulb + nt * 8;
            float d0 = sdp[ul], d1 = sdp[ul + 1];
            float w0 = sw2[ul], w1 = sw2[ul + 1];
            s0 += fast_tanh(acc[mt][nt][0] + d0) * w0 +
                  fast_tanh(acc[mt][nt][1] + d1) * w1;
            s1 += fast_tanh(acc[mt][nt][2] + d0) * w0 +
                  fast_tanh(acc[mt][nt][3] + d1) * w1;
        }
        s0 += __shfl_xor_sync(0xffffffffu, s0, 1);
        s0 += __shfl_xor_sync(0xffffffffu, s0, 2);
        s1 += __shfl_xor_sync(0xffffffffu, s1, 1);
        s1 += __shfl_xor_sync(0xffffffffu, s1, 2);
        if (lid4 == 0) {
            int r = wm * 32 + mt * 16 + lg;
            atomicAdd(&g_scores[b * CT + t0 + r], s0);
            atomicAdd(&g_scores[b * CT + t0 + r + 8], s1);
        }
    }
}

// -------------------- kernel 2: softmax (+ b2, relu) + zero context --------------------
__global__ void softmax_kernel(const float* __restrict__ b2, float* __restrict__ out) {
    const int b = blockIdx.x;
    const int tid = threadIdx.x;
    const int wid = tid >> 5, lid = tid & 31;
    __shared__ float wredm[8], wreds[8];
    const float b2v = b2[0];
    float sv[8];

    float mx = 0.f;                        // relu -> scores >= 0
#pragma unroll
    for (int q = 0; q < 8; q++) {
        float s = g_scores[b * CT + q * 256 + tid] + b2v;
        s = s > 0.f ? s : 0.f;
        sv[q] = s;
        mx = fmaxf(mx, s);
    }
#pragma unroll
    for (int off = 16; off >= 1; off >>= 1)
        mx = fmaxf(mx, __shfl_xor_sync(0xffffffffu, mx, off));
    if (lid == 0) wredm[wid] = mx;
    __syncthreads();
    float m = wredm[0];
#pragma unroll
    for (int i = 1; i < 8; i++) m = fmaxf(m, wredm[i]);

    float sum = 0.f;
#pragma unroll
    for (int q = 0; q < 8; q++) {
        float e = expf(sv[q] - m);
        sv[q] = e;
        sum += e;
    }
#pragma unroll
    for (int off = 16; off >= 1; off >>= 1)
        sum += __shfl_xor_sync(0xffffffffu, sum, off);
    if (lid == 0) wreds[wid] = sum;
    __syncthreads();
    float tot = 0.f;
#pragma unroll
    for (int i = 0; i < 8; i++) tot += wreds[i];
    const float inv = 1.f / tot;

    float* attn = out + (size_t)CB * CD + (size_t)b * CT;
#pragma unroll
    for (int q = 0; q < 8; q++) attn[q * 256 + tid] = sv[q] * inv;

    for (int i = tid; i < CD; i += 256) out[b * CD + i] = 0.f;
}

// -------------------- kernel 3: context = sum_t attn * h_enc(fp16) --------------------
// block = 256 threads: 64 d-slots (8 halves each) x 4 row-groups (32 rows).
// 8 uint4 loads in flight per thread (128B) -> high MLP.
__global__ __launch_bounds__(256)
void context_kernel(float* __restrict__ out) {
    const int b = blockIdx.y;
    const int t0 = blockIdx.x * 128;
    const int tid = threadIdx.x;
    const int dslot = tid & 63;            // d = dslot*8
    const int grp = tid >> 6;              // rows [grp*32, grp*32+32)
    __shared__ float at[128];
    __shared__ float sred[2][512];
    if (tid < 128) at[tid] = out[(size_t)CB * CD + (size_t)b * CT + t0 + tid];
    __syncthreads();

    const __half* hp = g_Ah + ((size_t)(b * CT + t0 + grp * 32)) * CD + dslot * 8;
    float acc[8];
#pragma unroll
    for (int k = 0; k < 8; k++) acc[k] = 0.f;

#pragma unroll 1
    for (int tt = 0; tt < 32; tt += 8) {
        uint4 hv[8];
#pragma unroll
        for (int j = 0; j < 8; j++)
            hv[j] = *(const uint4*)(hp + (size_t)(tt + j) * CD);
        float a[8];
#pragma unroll
        for (int j = 0; j < 8; j++) a[j] = at[grp * 32 + tt + j];
#pragma unroll
        for (int j = 0; j < 8; j++) {
            float2 f0 = __half22float2(*(__half2*)&hv[j].x);
            float2 f1 = __half22float2(*(__half2*)&hv[j].y);
            float2 f2 = __half22float2(*(__half2*)&hv[j].z);
            float2 f3 = __half22float2(*(__half2*)&hv[j].w);
            acc[0] += a[j] * f0.x;  acc[1] += a[j] * f0.y;
            acc[2] += a[j] * f1.x;  acc[3] += a[j] * f1.y;
            acc[4] += a[j] * f2.x;  acc[5] += a[j] * f2.y;
            acc[6] += a[j] * f3.x;  acc[7] += a[j] * f3.y;
        }
    }

    // combine 4 row-groups: (2,3) -> smem; (0,1) add; 1 -> smem; 0 adds + atomics
    if (grp >= 2) {
#pragma unroll
        for (int k = 0; k < 8; k++) sred[grp - 2][dslot * 8 + k] = acc[k];
    }
    __syncthreads();
    if (grp < 2) {
#pragma unroll
        for (int k = 0; k < 8; k++) acc[k] += sred[grp][dslot * 8 + k];
    }
    __syncthreads();
    if (grp == 1) {
#pragma unroll
        for (int k = 0; k < 8; k++) sred[0][dslot * 8 + k] = acc[k];
    }
    __syncthreads();
    if (grp == 0) {
        float* cp = out + (size_t)b * CD + dslot * 8;
#pragma unroll
        for (int k = 0; k < 8; k++)
            atomicAdd(cp + k, acc[k] + sred[0][dslot * 8 + k]);
    }
}

// -------------------- host launcher --------------------
extern "C" void kernel_launch(void* const* d_in, const int* in_sizes, int n_in,
                              void* d_out, int out_size) {
    const float* h_enc = (const float*)d_in[0];
    const float* h_dec = (const float*)d_in[1];
    const float* W1    = (const float*)d_in[2];
    const float* b1    = (const float*)d_in[3];
    const float* W2    = (const float*)d_in[4];
    const float* b2    = (const float*)d_in[5];
    float* out = (float*)d_out;

    cudaFuncSetAttribute(score_kernel,
                         cudaFuncAttributeMaxDynamicSharedMemorySize, SM_TOT);

    fused_prep_kernel<<<PREP_GRID, 256>>>(h_enc, W1, h_dec, b1);
    score_kernel<<<dim3(64, CB), 256, SM_TOT>>>(W2);
    softmax_kernel<<<CB, 256>>>(b2, out);
    context_kernel<<<dim3(CT / 128, CB), 256>>>(out);
}